// round 1
// baseline (speedup 1.0000x reference)
#include <cuda_runtime.h>
#include <cuda_bf16.h>
#include <math.h>

// ---------------------------------------------------------------------------
// ChildSumTreeLSTM: complete 4-ary tree, depth 8, I=H=256.
// N = 87381 nodes, leaves = 65536 at offset 21845.
// Strategy:
//   1) pack Wcat = [W_iou_x; W_fx] (1024x256) + folded biases
//   2) XW = x @ Wcat^T + bias   (one big GEMM, 87381x1024)
//   3) leaf level: elementwise from XW
//   4) for l=7..0: hsum gather, IOUH = hsum @ W_iou_h^T,
//      FH = h[children] @ W_fh^T (children are contiguous), fused combine
//   5) write c_root, h_root to d_out
// ---------------------------------------------------------------------------

#define N_NODES   87381
#define LEAF_OFF  21845
#define N_LEAVES  65536
#define KDIM      256

// --------------------------- device scratch --------------------------------
__device__ float g_XW[(size_t)N_NODES * 1024];        // ~358 MB
__device__ float g_h[(size_t)N_NODES * 256];          // ~86 MB
__device__ float g_c[(size_t)N_NODES * 256];          // ~86 MB
__device__ float g_hsum[(size_t)16384 * 256];         // 16 MB
__device__ float g_iouh[(size_t)16384 * 768];         // 48 MB
__device__ float g_fh[(size_t)65536 * 256];           // 64 MB
__device__ float g_Wcat[1024 * 256];
__device__ float g_bcat[1024];

__device__ __forceinline__ float sigmoidf(float v) {
    return 1.0f / (1.0f + expf(-v));
}

// --------------------------- pack weights ----------------------------------
__global__ void pack_w(const float* __restrict__ Wix, const float* __restrict__ bix,
                       const float* __restrict__ bih,
                       const float* __restrict__ Wfx, const float* __restrict__ bfx,
                       const float* __restrict__ bfh) {
    int idx = blockIdx.x * 256 + threadIdx.x;       // 1024*256 total
    int r = idx >> 8;
    int col = idx & 255;
    g_Wcat[idx] = (r < 768) ? Wix[idx] : Wfx[idx - 768 * 256];
    if (col == 0) {
        g_bcat[r] = (r < 768) ? (bix[r] + bih[r]) : (bfx[r - 768] + bfh[r - 768]);
    }
}

// --------------------------- SGEMM (NT): C = A*B^T (+bias) -----------------
// A: MxK row-major (K contiguous), B: NxK row-major, C: MxN, K = 256.
// 128x128 block tile, BK=8, 256 threads, 8x8 microtile.
#define BM 128
#define BN 128
#define BK 8

__global__ __launch_bounds__(256, 2)
void sgemm_nt(const float* __restrict__ A, const float* __restrict__ B,
              float* __restrict__ C, const float* __restrict__ bias,
              int M, int N) {
    __shared__ float As[BK][BM];
    __shared__ float Bs[BK][BN];

    const int tid = threadIdx.x;
    const int bm = blockIdx.y * BM;
    const int bn = blockIdx.x * BN;
    const int tx = tid & 15;        // 0..15 -> col groups of 8
    const int ty = tid >> 4;        // 0..15 -> row groups of 8

    const int lrow = tid >> 1;          // 0..127
    const int lkq  = (tid & 1) * 4;     // 0 or 4

    float acc[8][8];
#pragma unroll
    for (int i = 0; i < 8; i++)
#pragma unroll
        for (int j = 0; j < 8; j++) acc[i][j] = 0.0f;

    for (int k0 = 0; k0 < KDIM; k0 += BK) {
        float4 av = make_float4(0.f, 0.f, 0.f, 0.f);
        if (bm + lrow < M)
            av = *reinterpret_cast<const float4*>(&A[(size_t)(bm + lrow) * KDIM + k0 + lkq]);
        As[lkq + 0][lrow] = av.x;
        As[lkq + 1][lrow] = av.y;
        As[lkq + 2][lrow] = av.z;
        As[lkq + 3][lrow] = av.w;

        float4 bv = make_float4(0.f, 0.f, 0.f, 0.f);
        if (bn + lrow < N)
            bv = *reinterpret_cast<const float4*>(&B[(size_t)(bn + lrow) * KDIM + k0 + lkq]);
        Bs[lkq + 0][lrow] = bv.x;
        Bs[lkq + 1][lrow] = bv.y;
        Bs[lkq + 2][lrow] = bv.z;
        Bs[lkq + 3][lrow] = bv.w;

        __syncthreads();

#pragma unroll
        for (int kk = 0; kk < BK; kk++) {
            float4 a0 = *reinterpret_cast<const float4*>(&As[kk][ty * 8]);
            float4 a1 = *reinterpret_cast<const float4*>(&As[kk][ty * 8 + 4]);
            float4 b0 = *reinterpret_cast<const float4*>(&Bs[kk][tx * 8]);
            float4 b1 = *reinterpret_cast<const float4*>(&Bs[kk][tx * 8 + 4]);
            float af[8] = {a0.x, a0.y, a0.z, a0.w, a1.x, a1.y, a1.z, a1.w};
            float bf[8] = {b0.x, b0.y, b0.z, b0.w, b1.x, b1.y, b1.z, b1.w};
#pragma unroll
            for (int i = 0; i < 8; i++)
#pragma unroll
                for (int j = 0; j < 8; j++)
                    acc[i][j] = fmaf(af[i], bf[j], acc[i][j]);
        }
        __syncthreads();
    }

#pragma unroll
    for (int i = 0; i < 8; i++) {
        int r = bm + ty * 8 + i;
        if (r >= M) break;
#pragma unroll
        for (int j = 0; j < 8; j++) {
            int ccol = bn + tx * 8 + j;
            if (ccol < N) {
                float v = acc[i][j];
                if (bias) v += bias[ccol];
                C[(size_t)r * N + ccol] = v;
            }
        }
    }
}

// --------------------------- gather child_h sums ---------------------------
__global__ void gather_hsum(int child_off) {
    int idx = blockIdx.x * 256 + threadIdx.x;   // n * 256 threads
    const float* base = &g_h[((size_t)child_off + 4 * (size_t)blockIdx.x) * 256 + threadIdx.x];
    g_hsum[idx] = base[0] + base[256] + base[512] + base[768];
}

// --------------------------- leaf level ------------------------------------
__global__ void combine_leaf() {
    const size_t node = LEAF_OFF + blockIdx.x;
    const int j = threadIdx.x;
    const float* xw = &g_XW[node * 1024];
    float iv = sigmoidf(xw[j]);
    float ov = sigmoidf(xw[256 + j]);
    float uv = tanhf(xw[512 + j]);
    float c = iv * uv;
    float h = ov * tanhf(c);
    g_c[node * 256 + j] = c;
    g_h[node * 256 + j] = h;
}

// --------------------------- internal levels -------------------------------
__global__ void combine_level(int node_off, int child_off) {
    const int k = blockIdx.x;
    const int j = threadIdx.x;
    const size_t node = (size_t)node_off + k;
    const float* xw = &g_XW[node * 1024];
    const float* iouh = &g_iouh[(size_t)k * 768];

    float iv = sigmoidf(xw[j] + iouh[j]);
    float ov = sigmoidf(xw[256 + j] + iouh[256 + j]);
    float uv = tanhf(xw[512 + j] + iouh[512 + j]);
    float fx = xw[768 + j];

    float acc = 0.0f;
#pragma unroll
    for (int b = 0; b < 4; b++) {
        size_t ch = (size_t)child_off + 4 * (size_t)k + b;
        float f = sigmoidf(fx + g_fh[(4 * (size_t)k + b) * 256 + j]);
        acc = fmaf(f, g_c[ch * 256 + j], acc);
    }
    float c = fmaf(iv, uv, acc);
    float h = ov * tanhf(c);
    g_c[node * 256 + j] = c;
    g_h[node * 256 + j] = h;
}

// --------------------------- output ----------------------------------------
__global__ void write_out(float* __restrict__ out) {
    int j = threadIdx.x;
    if (blockIdx.x == 0) out[j] = g_c[j];           // c_root (node 0)
    else                 out[256 + j] = g_h[j];      // h_root
}

// --------------------------- launcher --------------------------------------
extern "C" void kernel_launch(void* const* d_in, const int* in_sizes, int n_in,
                              void* d_out, int out_size) {
    const float* x      = (const float*)d_in[0];
    const float* W_ioux = (const float*)d_in[1];
    const float* b_ioux = (const float*)d_in[2];
    const float* W_iouh = (const float*)d_in[3];
    const float* b_iouh = (const float*)d_in[4];
    const float* W_fx   = (const float*)d_in[5];
    const float* b_fx   = (const float*)d_in[6];
    const float* W_fh   = (const float*)d_in[7];
    const float* b_fh   = (const float*)d_in[8];

    float* g_XW_p;   cudaGetSymbolAddress((void**)&g_XW_p, g_XW);
    float* g_hsum_p; cudaGetSymbolAddress((void**)&g_hsum_p, g_hsum);
    float* g_iouh_p; cudaGetSymbolAddress((void**)&g_iouh_p, g_iouh);
    float* g_fh_p;   cudaGetSymbolAddress((void**)&g_fh_p, g_fh);
    float* g_h_p;    cudaGetSymbolAddress((void**)&g_h_p, g_h);
    float* g_Wcat_p; cudaGetSymbolAddress((void**)&g_Wcat_p, g_Wcat);
    float* g_bcat_p; cudaGetSymbolAddress((void**)&g_bcat_p, g_bcat);

    // 1) pack weights/biases
    pack_w<<<1024, 256>>>(W_ioux, b_ioux, b_iouh, W_fx, b_fx, b_fh);

    // 2) big GEMM: XW = x @ Wcat^T + bcat   (87381 x 1024)
    {
        dim3 grid(1024 / BN, (N_NODES + BM - 1) / BM);
        sgemm_nt<<<grid, 256>>>(x, g_Wcat_p, g_XW_p, g_bcat_p, N_NODES, 1024);
    }

    // 3) leaf level (l = 8)
    combine_leaf<<<N_LEAVES, 256>>>();

    // 4) internal levels l = 7..0
    for (int l = 7; l >= 0; l--) {
        int n = 1 << (2 * l);               // 4^l
        int off = ((1 << (2 * (l + 1))) - 1) / 3;  // wrong formula? compute directly below
        off = ((1 << (2 * l)) - 1) / 3;     // (4^l - 1)/3
        int choff = off + n;

        gather_hsum<<<n, 256>>>(choff);

        {   // IOUH = hsum @ W_iou_h^T  : (n x 768)
            dim3 grid(768 / BN, (n + BM - 1) / BM);
            sgemm_nt<<<grid, 256>>>(g_hsum_p, W_iouh, g_iouh_p, nullptr, n, 768);
        }
        {   // FH = h[children] @ W_fh^T : (4n x 256), children contiguous
            dim3 grid(256 / BN, (4 * n + BM - 1) / BM);
            sgemm_nt<<<grid, 256>>>(&g_h_p[(size_t)choff * 256], W_fh, g_fh_p,
                                    nullptr, 4 * n, 256);
        }
        combine_level<<<n, 256>>>(off, choff);
    }

    // 5) output: [c_root(256), h_root(256)]
    write_out<<<2, 256>>>((float*)d_out);
}

// round 3
// speedup vs baseline: 2.2745x; 2.2745x over previous
#include <cuda_runtime.h>
#include <cuda_bf16.h>
#include <math.h>
#include <stdint.h>

// ---------------------------------------------------------------------------
// ChildSumTreeLSTM via HMMA (mma.sync bf16) on sm_100 (plain target).
// fp32-accurate GEMMs via 3-term bf16 split, implemented as K-expansion:
//   A' = [Ah | Al | Ah]  (K=768),  B' = [Bh | Bh | Bl]  (K=768)
//   A'.B' = Ah.Bh + Al.Bh + Ah.Bl  ~= fp32 product
// ---------------------------------------------------------------------------

#define N_NODES   87381
#define LEAF_OFF  21845
#define N_LEAVES  65536
#define KTOT      768
#define NCHUNK    24          // 768 / 32
#define AROW_B    80          // smem row stride in bytes (40 bf16) - conflict free
#define STAGE_B   20480       // 128*80 (A) + handled: A at 0, B at 10240

// --------------------------- device scratch --------------------------------
__device__ __align__(256) float         g_XW[(size_t)N_NODES * 1024];
__device__ __align__(256) float         g_c [(size_t)N_NODES * 256];
__device__ __align__(256) __nv_bfloat16 g_h3[(size_t)N_NODES * KTOT];
__device__ __align__(256) __nv_bfloat16 g_x3[(size_t)N_NODES * KTOT];
__device__ __align__(256) __nv_bfloat16 g_hsum3[(size_t)16384 * KTOT];
__device__ __align__(256) float         g_iouh[(size_t)16384 * 768];
__device__ __align__(256) float         g_fh  [(size_t)65536 * 256];
__device__ __align__(256) __nv_bfloat16 g_Wcat3 [1024 * KTOT];
__device__ __align__(256) __nv_bfloat16 g_Wiouh3[ 768 * KTOT];
__device__ __align__(256) __nv_bfloat16 g_Wfh3  [ 256 * KTOT];
__device__ float g_bcat[1024];

// --------------------------- helpers ---------------------------------------
__device__ __forceinline__ float sigmoidf(float v) {
    return 1.0f / (1.0f + expf(-v));
}

// A-side layout: [hi | lo | hi]
__device__ __forceinline__ void writeA3(__nv_bfloat16* row, int j, float v) {
    __nv_bfloat16 hi = __float2bfloat16(v);
    __nv_bfloat16 lo = __float2bfloat16(v - __bfloat162float(hi));
    row[j] = hi; row[256 + j] = lo; row[512 + j] = hi;
}
// B-side layout: [hi | hi | lo]
__device__ __forceinline__ void writeB3(__nv_bfloat16* row, int j, float v) {
    __nv_bfloat16 hi = __float2bfloat16(v);
    __nv_bfloat16 lo = __float2bfloat16(v - __bfloat162float(hi));
    row[j] = hi; row[256 + j] = hi; row[512 + j] = lo;
}

__device__ __forceinline__ uint32_t smem_u32(const void* p) {
    uint32_t a;
    asm("{ .reg .u64 t; cvta.to.shared.u64 t, %1; cvt.u32.u64 %0, t; }" : "=r"(a) : "l"(p));
    return a;
}

__device__ __forceinline__ void cp_async16(uint32_t dst, const void* src, int sz) {
    asm volatile("cp.async.ca.shared.global [%0], [%1], 16, %2;"
                 :: "r"(dst), "l"(src), "r"(sz) : "memory");
}

__device__ __forceinline__ void ldmatrix_x4(uint32_t* r, uint32_t addr) {
    asm volatile("ldmatrix.sync.aligned.m8n8.x4.shared.b16 {%0,%1,%2,%3}, [%4];"
                 : "=r"(r[0]), "=r"(r[1]), "=r"(r[2]), "=r"(r[3]) : "r"(addr));
}

__device__ __forceinline__ void mma16816(float* c, const uint32_t* a, const uint32_t* b) {
    asm volatile(
        "mma.sync.aligned.m16n8k16.row.col.f32.bf16.bf16.f32 "
        "{%0,%1,%2,%3}, {%4,%5,%6,%7}, {%8,%9}, {%0,%1,%2,%3};"
        : "+f"(c[0]), "+f"(c[1]), "+f"(c[2]), "+f"(c[3])
        : "r"(a[0]), "r"(a[1]), "r"(a[2]), "r"(a[3]), "r"(b[0]), "r"(b[1]));
}

// --------------------------- pack kernels ----------------------------------
__global__ void split_x3(const float* __restrict__ x) {
    const size_t node = blockIdx.x;
    const int j = threadIdx.x;
    writeA3(&g_x3[node * KTOT], j, x[node * 256 + j]);
}

__global__ void pack_wcat3(const float* __restrict__ Wix, const float* __restrict__ bix,
                           const float* __restrict__ bih,
                           const float* __restrict__ Wfx, const float* __restrict__ bfx,
                           const float* __restrict__ bfh) {
    const int r = blockIdx.x;           // 0..1023
    const int j = threadIdx.x;
    float v = (r < 768) ? Wix[r * 256 + j] : Wfx[(r - 768) * 256 + j];
    writeB3(&g_Wcat3[(size_t)r * KTOT], j, v);
    if (j == 0)
        g_bcat[r] = (r < 768) ? (bix[r] + bih[r]) : (bfx[r - 768] + bfh[r - 768]);
}

__global__ void pack_wiouh3(const float* __restrict__ W) {
    const int r = blockIdx.x;
    const int j = threadIdx.x;
    writeB3(&g_Wiouh3[(size_t)r * KTOT], j, W[r * 256 + j]);
}

__global__ void pack_wfh3(const float* __restrict__ W) {
    const int r = blockIdx.x;
    const int j = threadIdx.x;
    writeB3(&g_Wfh3[(size_t)r * KTOT], j, W[r * 256 + j]);
}

// --------------------------- HMMA GEMM -------------------------------------
// C[M x Ntot] = A3 @ B3^T (+bias). A3: [M][768] bf16, B3: [Ntot][768] bf16.
// CTA tile 128x128, 256 threads (8 warps, 4x2), warp tile 32x64.
// K chunk 32, 2-stage cp.async pipeline.
__global__ __launch_bounds__(256, 2)
void gemm_hmma(const __nv_bfloat16* __restrict__ A, const __nv_bfloat16* __restrict__ B,
               float* __restrict__ C, const float* __restrict__ bias,
               int M, int Ntot) {
    __shared__ __align__(16) char sm[2][STAGE_B];

    const int tid  = threadIdx.x;
    const int wid  = tid >> 5;
    const int lane = tid & 31;
    const int bm = blockIdx.y * 128;
    const int bn = blockIdx.x * 128;
    const int wm = (wid >> 1) * 32;
    const int wn = (wid & 1) * 64;

    const uint32_t sb = smem_u32(sm);

    float acc[2][8][4];
#pragma unroll
    for (int i = 0; i < 2; i++)
#pragma unroll
        for (int n = 0; n < 8; n++)
#pragma unroll
            for (int q = 0; q < 4; q++) acc[i][n][q] = 0.0f;

    // per-thread load slots: 2 A segs + 2 B segs per stage
    const int s0 = tid, s1 = tid + 256;
    const int r0 = s0 >> 2, q0 = s0 & 3;
    const int r1 = s1 >> 2, q1 = s1 & 3;
    const int szA0 = (bm + r0 < M) ? 16 : 0;
    const int szA1 = (bm + r1 < M) ? 16 : 0;

#define LOAD_CHUNK(c, st) do {                                                   \
        const int k0 = (c) * 32;                                                 \
        uint32_t ab = sb + (st) * STAGE_B;                                       \
        uint32_t bb = ab + 10240;                                                \
        cp_async16(ab + r0 * AROW_B + q0 * 16,                                   \
                   A + (size_t)(bm + r0) * KTOT + k0 + q0 * 8, szA0);            \
        cp_async16(ab + r1 * AROW_B + q1 * 16,                                   \
                   A + (size_t)(bm + r1) * KTOT + k0 + q1 * 8, szA1);            \
        cp_async16(bb + r0 * AROW_B + q0 * 16,                                   \
                   B + (size_t)(bn + r0) * KTOT + k0 + q0 * 8, 16);              \
        cp_async16(bb + r1 * AROW_B + q1 * 16,                                   \
                   B + (size_t)(bn + r1) * KTOT + k0 + q1 * 8, 16);              \
        asm volatile("cp.async.commit_group;" ::: "memory");                     \
    } while (0)

    LOAD_CHUNK(0, 0);

    const uint32_t lrow = lane & 15;
    const uint32_t lcol = (lane >> 4) * 16;

    for (int c = 0; c < NCHUNK; c++) {
        const int st = c & 1;
        if (c + 1 < NCHUNK) {
            LOAD_CHUNK(c + 1, st ^ 1);
            asm volatile("cp.async.wait_group 1;" ::: "memory");
        } else {
            asm volatile("cp.async.wait_group 0;" ::: "memory");
        }
        __syncthreads();

        const uint32_t abase = sb + st * STAGE_B + (wm + lrow) * AROW_B + lcol;
        const uint32_t bbase = sb + st * STAGE_B + 10240 + (wn + lrow) * AROW_B + lcol;

#pragma unroll
        for (int ks = 0; ks < 2; ks++) {
            const uint32_t ko = ks * 32;
            uint32_t a[2][4];
            ldmatrix_x4(a[0], abase + ko);
            ldmatrix_x4(a[1], abase + 16 * AROW_B + ko);
            uint32_t bf[8][2];
#pragma unroll
            for (int j = 0; j < 4; j++) {
                uint32_t r[4];
                ldmatrix_x4(r, bbase + j * 16 * AROW_B + ko);
                bf[2 * j][0] = r[0]; bf[2 * j][1] = r[2];
                bf[2 * j + 1][0] = r[1]; bf[2 * j + 1][1] = r[3];
            }
#pragma unroll
            for (int i = 0; i < 2; i++)
#pragma unroll
                for (int n = 0; n < 8; n++)
                    mma16816(acc[i][n], a[i], bf[n]);
        }
        __syncthreads();
    }

    // epilogue
#pragma unroll
    for (int i = 0; i < 2; i++) {
        const int ra = bm + wm + i * 16 + (lane >> 2);
        const int rb = ra + 8;
#pragma unroll
        for (int n = 0; n < 8; n++) {
            const int col = bn + wn + n * 8 + (lane & 3) * 2;
            float b0 = 0.f, b1 = 0.f;
            if (bias) { b0 = bias[col]; b1 = bias[col + 1]; }
            if (ra < M)
                *(float2*)(C + (size_t)ra * Ntot + col) =
                    make_float2(acc[i][n][0] + b0, acc[i][n][1] + b1);
            if (rb < M)
                *(float2*)(C + (size_t)rb * Ntot + col) =
                    make_float2(acc[i][n][2] + b0, acc[i][n][3] + b1);
        }
    }
#undef LOAD_CHUNK
}

// --------------------------- elementwise kernels ---------------------------
__global__ void combine_leaf() {
    const size_t node = LEAF_OFF + blockIdx.x;
    const int j = threadIdx.x;
    const float* xw = &g_XW[node * 1024];
    float iv = sigmoidf(xw[j]);
    float ov = sigmoidf(xw[256 + j]);
    float uv = tanhf(xw[512 + j]);
    float c = iv * uv;
    float h = ov * tanhf(c);
    g_c[node * 256 + j] = c;
    writeA3(&g_h3[node * KTOT], j, h);
}

__global__ void gather_hsum(int child_off) {
    const int k = blockIdx.x;
    const int j = threadIdx.x;
    const __nv_bfloat16* base = &g_h3[((size_t)child_off + 4 * (size_t)k) * KTOT];
    float s = 0.0f;
#pragma unroll
    for (int b = 0; b < 4; b++) {
        const __nv_bfloat16* row = base + (size_t)b * KTOT;
        s += __bfloat162float(row[j]) + __bfloat162float(row[256 + j]);
    }
    writeA3(&g_hsum3[(size_t)k * KTOT], j, s);
}

__global__ void combine_level(int node_off, int child_off) {
    const int k = blockIdx.x;
    const int j = threadIdx.x;
    const size_t node = (size_t)node_off + k;
    const float* xw = &g_XW[node * 1024];
    const float* iouh = &g_iouh[(size_t)k * 768];

    float iv = sigmoidf(xw[j] + iouh[j]);
    float ov = sigmoidf(xw[256 + j] + iouh[256 + j]);
    float uv = tanhf(xw[512 + j] + iouh[512 + j]);
    float fx = xw[768 + j];

    float acc = 0.0f;
#pragma unroll
    for (int b = 0; b < 4; b++) {
        size_t ch = (size_t)child_off + 4 * (size_t)k + b;
        float f = sigmoidf(fx + g_fh[(4 * (size_t)k + b) * 256 + j]);
        acc = fmaf(f, g_c[ch * 256 + j], acc);
    }
    float c = fmaf(iv, uv, acc);
    float h = ov * tanhf(c);
    g_c[node * 256 + j] = c;
    writeA3(&g_h3[node * KTOT], j, h);
}

__global__ void write_out(float* __restrict__ out) {
    int j = threadIdx.x;
    if (blockIdx.x == 0) out[j] = g_c[j];
    else out[256 + j] = __bfloat162float(g_h3[j]) + __bfloat162float(g_h3[256 + j]);
}

// --------------------------- launcher --------------------------------------
extern "C" void kernel_launch(void* const* d_in, const int* in_sizes, int n_in,
                              void* d_out, int out_size) {
    const float* x      = (const float*)d_in[0];
    const float* W_ioux = (const float*)d_in[1];
    const float* b_ioux = (const float*)d_in[2];
    const float* W_iouh = (const float*)d_in[3];
    const float* b_iouh = (const float*)d_in[4];
    const float* W_fx   = (const float*)d_in[5];
    const float* b_fx   = (const float*)d_in[6];
    const float* W_fh   = (const float*)d_in[7];
    const float* b_fh   = (const float*)d_in[8];

    __nv_bfloat16 *x3, *h3, *hs3, *wc3, *wi3, *wf3;
    float *xw, *bcat, *iouh, *fh;
    cudaGetSymbolAddress((void**)&x3,   g_x3);
    cudaGetSymbolAddress((void**)&h3,   g_h3);
    cudaGetSymbolAddress((void**)&hs3,  g_hsum3);
    cudaGetSymbolAddress((void**)&wc3,  g_Wcat3);
    cudaGetSymbolAddress((void**)&wi3,  g_Wiouh3);
    cudaGetSymbolAddress((void**)&wf3,  g_Wfh3);
    cudaGetSymbolAddress((void**)&xw,   g_XW);
    cudaGetSymbolAddress((void**)&bcat, g_bcat);
    cudaGetSymbolAddress((void**)&iouh, g_iouh);
    cudaGetSymbolAddress((void**)&fh,   g_fh);

    // pack / split inputs
    split_x3<<<N_NODES, 256>>>(x);
    pack_wcat3<<<1024, 256>>>(W_ioux, b_ioux, b_iouh, W_fx, b_fx, b_fh);
    pack_wiouh3<<<768, 256>>>(W_iouh);
    pack_wfh3<<<256, 256>>>(W_fh);

    // big GEMM: XW = x @ Wcat^T + bcat  (87381 x 1024)
    {
        dim3 grid(1024 / 128, (N_NODES + 127) / 128);
        gemm_hmma<<<grid, 256>>>(x3, wc3, xw, bcat, N_NODES, 1024);
    }

    // leaf level
    combine_leaf<<<N_LEAVES, 256>>>();

    // internal levels l = 7..0
    for (int l = 7; l >= 0; l--) {
        int n = 1 << (2 * l);
        int off = ((1 << (2 * l)) - 1) / 3;
        int choff = off + n;

        gather_hsum<<<n, 256>>>(choff);

        {   // IOUH = hsum @ W_iou_h^T : (n x 768)
            dim3 grid(768 / 128, (n + 127) / 128);
            gemm_hmma<<<grid, 256>>>(hs3, wi3, iouh, nullptr, n, 768);
        }
        {   // FH = h[children] @ W_fh^T : (4n x 256)
            dim3 grid(256 / 128, (4 * n + 127) / 128);
            gemm_hmma<<<grid, 256>>>(&h3[(size_t)choff * KTOT], wf3, fh,
                                     nullptr, 4 * n, 256);
        }
        combine_level<<<n, 256>>>(off, choff);
    }

    write_out<<<2, 256>>>((float*)d_out);
}

// round 5
// speedup vs baseline: 2.5242x; 1.1098x over previous
#include <cuda_runtime.h>
#include <cuda_bf16.h>
#include <math.h>
#include <stdint.h>

// ---------------------------------------------------------------------------
// ChildSumTreeLSTM via HMMA (mma.sync bf16), fp32 accuracy via 3-term split:
//   A' = [Ah | Al | Ah] (K=768), B' = [Bh | Bh | Bl] (K=768)
// Big GEMM uses gate-interleaved Wcat columns (4j+g) so the epilogue can apply
// the leaf activation in-place (no XW round trip for 75% of rows).
// ---------------------------------------------------------------------------

#define N_NODES   87381
#define LEAF_OFF  21845
#define N_LEAVES  65536
#define KTOT      768
#define NCHUNK    24          // 768 / 32
#define AROW_B    80          // smem row stride (bytes) - conflict-free ldmatrix
#define STAGE_B   20480       // 128*80 * 2 (A tile + B tile)
#define SPITCH    132         // epilogue staging row pitch (floats)
#define BIG_SMEM  (SPITCH * 128 * 4)   // 67584 >= 3*STAGE_B (61440)

// --------------------------- device scratch --------------------------------
__device__ __align__(256) float         g_XW[(size_t)N_NODES * 1024];   // gate-interleaved
__device__ __align__(256) float         g_c [(size_t)N_NODES * 256];
__device__ __align__(256) __nv_bfloat16 g_h3[(size_t)N_NODES * KTOT];
__device__ __align__(256) __nv_bfloat16 g_x3[(size_t)N_NODES * KTOT];
__device__ __align__(256) __nv_bfloat16 g_hsum3[(size_t)16384 * KTOT];
__device__ __align__(256) float         g_iouh[(size_t)16384 * 768];    // 3j+g interleaved
__device__ __align__(256) float         g_fh  [(size_t)65536 * 256];
__device__ __align__(256) __nv_bfloat16 g_Wcat3 [1024 * KTOT];          // rows = 4j+g
__device__ __align__(256) __nv_bfloat16 g_Wiouh3[ 768 * KTOT];          // rows = 3j+g
__device__ __align__(256) __nv_bfloat16 g_Wfh3  [ 256 * KTOT];
__device__ float g_bcat[1024];                                          // 4j+g

// --------------------------- helpers ---------------------------------------
__device__ __forceinline__ float sigmoidf(float v) {
    return 1.0f / (1.0f + expf(-v));
}
__device__ __forceinline__ void writeA3(__nv_bfloat16* row, int j, float v) {
    __nv_bfloat16 hi = __float2bfloat16(v);
    __nv_bfloat16 lo = __float2bfloat16(v - __bfloat162float(hi));
    row[j] = hi; row[256 + j] = lo; row[512 + j] = hi;
}
__device__ __forceinline__ void writeB3(__nv_bfloat16* row, int j, float v) {
    __nv_bfloat16 hi = __float2bfloat16(v);
    __nv_bfloat16 lo = __float2bfloat16(v - __bfloat162float(hi));
    row[j] = hi; row[256 + j] = hi; row[512 + j] = lo;
}
__device__ __forceinline__ uint32_t smem_u32(const void* p) {
    uint32_t a;
    asm("{ .reg .u64 t; cvta.to.shared.u64 t, %1; cvt.u32.u64 %0, t; }" : "=r"(a) : "l"(p));
    return a;
}
__device__ __forceinline__ void cp_async16(uint32_t dst, const void* src, int sz) {
    asm volatile("cp.async.ca.shared.global [%0], [%1], 16, %2;"
                 :: "r"(dst), "l"(src), "r"(sz) : "memory");
}
__device__ __forceinline__ void ldmatrix_x4(uint32_t* r, uint32_t addr) {
    asm volatile("ldmatrix.sync.aligned.m8n8.x4.shared.b16 {%0,%1,%2,%3}, [%4];"
                 : "=r"(r[0]), "=r"(r[1]), "=r"(r[2]), "=r"(r[3]) : "r"(addr));
}
__device__ __forceinline__ void mma16816(float* c, const uint32_t* a, const uint32_t* b) {
    asm volatile(
        "mma.sync.aligned.m16n8k16.row.col.f32.bf16.bf16.f32 "
        "{%0,%1,%2,%3}, {%4,%5,%6,%7}, {%8,%9}, {%0,%1,%2,%3};"
        : "+f"(c[0]), "+f"(c[1]), "+f"(c[2]), "+f"(c[3])
        : "r"(a[0]), "r"(a[1]), "r"(a[2]), "r"(a[3]), "r"(b[0]), "r"(b[1]));
}

// --------------------------- pack kernels ----------------------------------
__global__ void split_x3(const float* __restrict__ x) {
    const size_t node = blockIdx.x;
    const int j = threadIdx.x;
    writeA3(&g_x3[node * KTOT], j, x[node * 256 + j]);
}

// Wcat rows p = 4j+g:  g<3 -> W_iou_x row g*256+j ; g==3 -> W_fx row j
__global__ void pack_wcat3(const float* __restrict__ Wix, const float* __restrict__ bix,
                           const float* __restrict__ bih,
                           const float* __restrict__ Wfx, const float* __restrict__ bfx,
                           const float* __restrict__ bfh) {
    const int p = blockIdx.x;           // 0..1023
    const int jj = threadIdx.x;         // column 0..255
    const int j = p >> 2, g = p & 3;
    float v = (g < 3) ? Wix[(g * 256 + j) * 256 + jj] : Wfx[j * 256 + jj];
    writeB3(&g_Wcat3[(size_t)p * KTOT], jj, v);
    if (jj == 0)
        g_bcat[p] = (g < 3) ? (bix[g * 256 + j] + bih[g * 256 + j]) : (bfx[j] + bfh[j]);
}

// Wiouh rows p = 3j+g -> W_iouh row g*256+j
__global__ void pack_wiouh3(const float* __restrict__ W) {
    const int p = blockIdx.x;           // 0..767
    const int jj = threadIdx.x;
    const int j = p / 3, g = p % 3;
    writeB3(&g_Wiouh3[(size_t)p * KTOT], jj, W[(g * 256 + j) * 256 + jj]);
}

__global__ void pack_wfh3(const float* __restrict__ W) {
    const int r = blockIdx.x;
    const int j = threadIdx.x;
    writeB3(&g_Wfh3[(size_t)r * KTOT], j, W[r * 256 + j]);
}

// --------------------------- GEMM core (2-stage, direct epilogue) ----------
__device__ __forceinline__ void gemm_core(const __nv_bfloat16* __restrict__ A,
                                          const __nv_bfloat16* __restrict__ B,
                                          float* __restrict__ C,
                                          int M, int Ntot, int bm, int bn,
                                          char* sm) {
    const int tid  = threadIdx.x;
    const int wid  = tid >> 5;
    const int lane = tid & 31;
    const int wm = (wid >> 1) * 32;
    const int wn = (wid & 1) * 64;
    const uint32_t sb = smem_u32(sm);

    float acc[2][8][4];
#pragma unroll
    for (int i = 0; i < 2; i++)
#pragma unroll
        for (int n = 0; n < 8; n++)
#pragma unroll
            for (int q = 0; q < 4; q++) acc[i][n][q] = 0.0f;

    const int r0 = tid >> 2, q0 = tid & 3;
    const int r1 = (tid + 256) >> 2, q1 = tid & 3;
    const int szA0 = (bm + r0 < M) ? 16 : 0;
    const int szA1 = (bm + r1 < M) ? 16 : 0;

#define LOAD2(c, st) do {                                                        \
        const int k0 = (c) * 32;                                                 \
        uint32_t ab = sb + (st) * STAGE_B;                                       \
        uint32_t bb = ab + 10240;                                                \
        cp_async16(ab + r0 * AROW_B + q0 * 16,                                   \
                   A + (size_t)(bm + r0) * KTOT + k0 + q0 * 8, szA0);            \
        cp_async16(ab + r1 * AROW_B + q1 * 16,                                   \
                   A + (size_t)(bm + r1) * KTOT + k0 + q1 * 8, szA1);            \
        cp_async16(bb + r0 * AROW_B + q0 * 16,                                   \
                   B + (size_t)(bn + r0) * KTOT + k0 + q0 * 8, 16);              \
        cp_async16(bb + r1 * AROW_B + q1 * 16,                                   \
                   B + (size_t)(bn + r1) * KTOT + k0 + q1 * 8, 16);              \
        asm volatile("cp.async.commit_group;" ::: "memory");                     \
    } while (0)

    LOAD2(0, 0);
    const uint32_t lrow = lane & 15;
    const uint32_t lcol = (lane >> 4) * 16;

    for (int c = 0; c < NCHUNK; c++) {
        const int st = c & 1;
        if (c + 1 < NCHUNK) {
            LOAD2(c + 1, st ^ 1);
            asm volatile("cp.async.wait_group 1;" ::: "memory");
        } else {
            asm volatile("cp.async.wait_group 0;" ::: "memory");
        }
        __syncthreads();

        const uint32_t abase = sb + st * STAGE_B + (wm + lrow) * AROW_B + lcol;
        const uint32_t bbase = sb + st * STAGE_B + 10240 + (wn + lrow) * AROW_B + lcol;
#pragma unroll
        for (int ks = 0; ks < 2; ks++) {
            const uint32_t ko = ks * 32;
            uint32_t a[2][4];
            ldmatrix_x4(a[0], abase + ko);
            ldmatrix_x4(a[1], abase + 16 * AROW_B + ko);
            uint32_t bf[8][2];
#pragma unroll
            for (int j = 0; j < 4; j++) {
                uint32_t r[4];
                ldmatrix_x4(r, bbase + j * 16 * AROW_B + ko);
                bf[2 * j][0] = r[0]; bf[2 * j][1] = r[2];
                bf[2 * j + 1][0] = r[1]; bf[2 * j + 1][1] = r[3];
            }
#pragma unroll
            for (int i = 0; i < 2; i++)
#pragma unroll
                for (int n = 0; n < 8; n++)
                    mma16816(acc[i][n], a[i], bf[n]);
        }
        __syncthreads();
    }
#undef LOAD2

#pragma unroll
    for (int i = 0; i < 2; i++) {
        const int ra = bm + wm + i * 16 + (lane >> 2);
        const int rb = ra + 8;
#pragma unroll
        for (int n = 0; n < 8; n++) {
            const int col = bn + wn + n * 8 + (lane & 3) * 2;
            if (ra < M)
                *(float2*)(C + (size_t)ra * Ntot + col) =
                    make_float2(acc[i][n][0], acc[i][n][1]);
            if (rb < M)
                *(float2*)(C + (size_t)rb * Ntot + col) =
                    make_float2(acc[i][n][2], acc[i][n][3]);
        }
    }
}

// --------------------------- dual-problem GEMM -----------------------------
__global__ __launch_bounds__(256, 2)
void gemm_dual(const __nv_bfloat16* A1, const __nv_bfloat16* B1, float* C1, int M1, int N1,
               const __nv_bfloat16* A2, const __nv_bfloat16* B2, float* C2, int M2, int N2) {
    __shared__ __align__(16) char sm[2 * STAGE_B];
    const int nt1 = N1 >> 7, mt1 = (M1 + 127) >> 7;
    const int t1 = nt1 * mt1;
    int idx = blockIdx.x;
    if (idx < t1) {
        gemm_core(A1, B1, C1, M1, N1, (idx / nt1) * 128, (idx % nt1) * 128, sm);
    } else {
        idx -= t1;
        const int nt2 = N2 >> 7;
        gemm_core(A2, B2, C2, M2, N2, (idx / nt2) * 128, (idx % nt2) * 128, sm);
    }
}

// --------------------------- big GEMM (3-stage, fused leaf epilogue) -------
__global__ __launch_bounds__(256, 2)
void gemm_big(const __nv_bfloat16* __restrict__ A, const __nv_bfloat16* __restrict__ B) {
    extern __shared__ __align__(16) char smd[];
    const int tid  = threadIdx.x;
    const int wid  = tid >> 5;
    const int lane = tid & 31;
    const int bm = blockIdx.y * 128;
    const int bn = blockIdx.x * 128;
    const int wm = (wid >> 1) * 32;
    const int wn = (wid & 1) * 64;
    const int M = N_NODES;
    const uint32_t sb = smem_u32(smd);

    float acc[2][8][4];
#pragma unroll
    for (int i = 0; i < 2; i++)
#pragma unroll
        for (int n = 0; n < 8; n++)
#pragma unroll
            for (int q = 0; q < 4; q++) acc[i][n][q] = 0.0f;

    const int r0 = tid >> 2, q0 = tid & 3;
    const int r1 = (tid + 256) >> 2;
    const int szA0 = (bm + r0 < M) ? 16 : 0;
    const int szA1 = (bm + r1 < M) ? 16 : 0;

#define LOAD3(c, st) do {                                                        \
        const int k0 = (c) * 32;                                                 \
        uint32_t ab = sb + (st) * STAGE_B;                                       \
        uint32_t bb = ab + 10240;                                                \
        cp_async16(ab + r0 * AROW_B + q0 * 16,                                   \
                   A + (size_t)(bm + r0) * KTOT + k0 + q0 * 8, szA0);            \
        cp_async16(ab + r1 * AROW_B + q0 * 16,                                   \
                   A + (size_t)(bm + r1) * KTOT + k0 + q0 * 8, szA1);            \
        cp_async16(bb + r0 * AROW_B + q0 * 16,                                   \
                   B + (size_t)(bn + r0) * KTOT + k0 + q0 * 8, 16);              \
        cp_async16(bb + r1 * AROW_B + q0 * 16,                                   \
                   B + (size_t)(bn + r1) * KTOT + k0 + q0 * 8, 16);              \
        asm volatile("cp.async.commit_group;" ::: "memory");                     \
    } while (0)

    LOAD3(0, 0);
    LOAD3(1, 1);
    const uint32_t lrow = lane & 15;
    const uint32_t lcol = (lane >> 4) * 16;

    for (int c = 0; c < NCHUNK; c++) {
        const int st = c % 3;
        if (c + 2 < NCHUNK) {
            LOAD3(c + 2, (c + 2) % 3);
            asm volatile("cp.async.wait_group 2;" ::: "memory");
        } else if (c + 1 < NCHUNK) {
            asm volatile("cp.async.wait_group 1;" ::: "memory");
        } else {
            asm volatile("cp.async.wait_group 0;" ::: "memory");
        }
        __syncthreads();

        const uint32_t abase = sb + st * STAGE_B + (wm + lrow) * AROW_B + lcol;
        const uint32_t bbase = sb + st * STAGE_B + 10240 + (wn + lrow) * AROW_B + lcol;
#pragma unroll
        for (int ks = 0; ks < 2; ks++) {
            const uint32_t ko = ks * 32;
            uint32_t a[2][4];
            ldmatrix_x4(a[0], abase + ko);
            ldmatrix_x4(a[1], abase + 16 * AROW_B + ko);
            uint32_t bf[8][2];
#pragma unroll
            for (int j = 0; j < 4; j++) {
                uint32_t r[4];
                ldmatrix_x4(r, bbase + j * 16 * AROW_B + ko);
                bf[2 * j][0] = r[0]; bf[2 * j][1] = r[2];
                bf[2 * j + 1][0] = r[1]; bf[2 * j + 1][1] = r[3];
            }
#pragma unroll
            for (int i = 0; i < 2; i++)
#pragma unroll
                for (int n = 0; n < 8; n++)
                    mma16816(acc[i][n], a[i], bf[n]);
        }
        __syncthreads();
    }
#undef LOAD3

    // ---- stage C tile into smem (aliases pipeline buffers; all dead now) ----
    float* Cs = (float*)smd;
#pragma unroll
    for (int i = 0; i < 2; i++) {
        const int ral = wm + i * 16 + (lane >> 2);
#pragma unroll
        for (int n = 0; n < 8; n++) {
            const int col = wn + n * 8 + (lane & 3) * 2;
            *(float2*)(Cs + ral * SPITCH + col) = make_float2(acc[i][n][0], acc[i][n][1]);
            *(float2*)(Cs + (ral + 8) * SPITCH + col) = make_float2(acc[i][n][2], acc[i][n][3]);
        }
    }
    __syncthreads();

    // ---- process: leaf rows -> activation; internal rows -> store XW ------
    const int j0 = bn >> 2;     // first feature index in this tile
#pragma unroll 4
    for (int it = 0; it < 16; it++) {
        const int idx = it * 256 + tid;
        const int r = idx >> 5;          // 0..127
        const int t = idx & 31;          // tuple 0..31
        const int row = bm + r;
        if (row >= M) continue;
        float4 v = *(float4*)(Cs + r * SPITCH + 4 * t);
        const float4 b = *(const float4*)(g_bcat + bn + 4 * t);
        v.x += b.x; v.y += b.y; v.z += b.z; v.w += b.w;
        if (row >= LEAF_OFF) {
            const int j = j0 + t;
            float iv = sigmoidf(v.x);
            float ov = sigmoidf(v.y);
            float uv = tanhf(v.z);
            float cc = iv * uv;
            float hh = ov * tanhf(cc);
            g_c[(size_t)row * 256 + j] = cc;
            writeA3(&g_h3[(size_t)row * KTOT], j, hh);
        } else {
            *(float4*)(g_XW + (size_t)row * 1024 + bn + 4 * t) = v;
        }
    }
}

// --------------------------- fused combine + parent hsum -------------------
// Block: 4 siblings x 256 features. Grid: n/4 (n = nodes at this level, >=4).
__global__ void combine_fused(int node_off, int child_off) {
    __shared__ float hsm[4][256];
    const int s = threadIdx.x >> 8;        // sibling 0..3
    const int j = threadIdx.x & 255;
    const int k = 4 * blockIdx.x + s;      // within-level node index
    const size_t node = (size_t)node_off + k;

    const float4 xw = *(const float4*)(g_XW + node * 1024 + 4 * j);
    const float* iouh = &g_iouh[(size_t)k * 768 + 3 * j];

    float iv = sigmoidf(xw.x + iouh[0]);
    float ov = sigmoidf(xw.y + iouh[1]);
    float uv = tanhf(xw.z + iouh[2]);
    const float fx = xw.w;

    float acc = 0.0f;
#pragma unroll
    for (int b = 0; b < 4; b++) {
        size_t ch = (size_t)child_off + 4 * (size_t)k + b;
        float f = sigmoidf(fx + g_fh[(4 * (size_t)k + b) * 256 + j]);
        acc = fmaf(f, g_c[ch * 256 + j], acc);
    }
    float c = fmaf(iv, uv, acc);
    float h = ov * tanhf(c);
    g_c[node * 256 + j] = c;
    writeA3(&g_h3[node * KTOT], j, h);

    hsm[s][j] = h;
    __syncthreads();
    if (s == 0) {
        float sum = hsm[0][j] + hsm[1][j] + hsm[2][j] + hsm[3][j];
        writeA3(&g_hsum3[(size_t)blockIdx.x * KTOT], j, sum);
    }
}

// Root (level 0, single node) — no parent hsum.
__global__ void combine_root() {
    const int j = threadIdx.x;
    const float4 xw = *(const float4*)(g_XW + 4 * j);
    const float* iouh = &g_iouh[3 * j];
    float iv = sigmoidf(xw.x + iouh[0]);
    float ov = sigmoidf(xw.y + iouh[1]);
    float uv = tanhf(xw.z + iouh[2]);
    const float fx = xw.w;
    float acc = 0.0f;
#pragma unroll
    for (int b = 0; b < 4; b++) {
        float f = sigmoidf(fx + g_fh[b * 256 + j]);
        acc = fmaf(f, g_c[(1 + b) * 256 + j], acc);
    }
    float c = fmaf(iv, uv, acc);
    float h = ov * tanhf(c);
    g_c[j] = c;
    writeA3(&g_h3[0], j, h);
}

// hsum for level 7 from leaf h (leaf groups not tile-aligned in big GEMM).
__global__ void gather_hsum_leaf() {
    const int k = blockIdx.x;              // 0..16383
    const int j = threadIdx.x;
    const __nv_bfloat16* base = &g_h3[((size_t)LEAF_OFF + 4 * (size_t)k) * KTOT];
    float s = 0.0f;
#pragma unroll
    for (int b = 0; b < 4; b++) {
        const __nv_bfloat16* row = base + (size_t)b * KTOT;
        s += __bfloat162float(row[j]) + __bfloat162float(row[256 + j]);
    }
    writeA3(&g_hsum3[(size_t)k * KTOT], j, s);
}

__global__ void write_out(float* __restrict__ out) {
    int j = threadIdx.x;
    if (blockIdx.x == 0) out[j] = g_c[j];
    else out[256 + j] = __bfloat162float(g_h3[j]) + __bfloat162float(g_h3[256 + j]);
}

// --------------------------- launcher --------------------------------------
extern "C" void kernel_launch(void* const* d_in, const int* in_sizes, int n_in,
                              void* d_out, int out_size) {
    const float* x      = (const float*)d_in[0];
    const float* W_ioux = (const float*)d_in[1];
    const float* b_ioux = (const float*)d_in[2];
    const float* W_iouh = (const float*)d_in[3];
    const float* b_iouh = (const float*)d_in[4];
    const float* W_fx   = (const float*)d_in[5];
    const float* b_fx   = (const float*)d_in[6];
    const float* W_fh   = (const float*)d_in[7];
    const float* b_fh   = (const float*)d_in[8];

    cudaFuncSetAttribute(gemm_big, cudaFuncAttributeMaxDynamicSharedMemorySize, BIG_SMEM);

    __nv_bfloat16 *x3, *h3, *hs3, *wc3, *wi3, *wf3;
    float *iouh, *fh;
    cudaGetSymbolAddress((void**)&x3,   g_x3);
    cudaGetSymbolAddress((void**)&h3,   g_h3);
    cudaGetSymbolAddress((void**)&hs3,  g_hsum3);
    cudaGetSymbolAddress((void**)&wc3,  g_Wcat3);
    cudaGetSymbolAddress((void**)&wi3,  g_Wiouh3);
    cudaGetSymbolAddress((void**)&wf3,  g_Wfh3);
    cudaGetSymbolAddress((void**)&iouh, g_iouh);
    cudaGetSymbolAddress((void**)&fh,   g_fh);

    // pack / split inputs
    split_x3<<<N_NODES, 256>>>(x);
    pack_wcat3<<<1024, 256>>>(W_ioux, b_ioux, b_iouh, W_fx, b_fx, b_fh);
    pack_wiouh3<<<768, 256>>>(W_iouh);
    pack_wfh3<<<256, 256>>>(W_fh);

    // big GEMM with fused leaf epilogue (gate-interleaved columns)
    {
        dim3 grid(8, (N_NODES + 127) / 128);
        gemm_big<<<grid, 256, BIG_SMEM>>>(x3, wc3);
    }

    // hsum for level 7 (children = leaves)
    gather_hsum_leaf<<<16384, 256>>>();

    // internal levels l = 7..0
    for (int l = 7; l >= 0; l--) {
        int n = 1 << (2 * l);
        int off = ((1 << (2 * l)) - 1) / 3;
        int choff = off + n;

        {   // fused dual GEMM: IOUH (n x 768) + FH (4n x 256)
            int mt1 = (n + 127) / 128;
            int mt2 = (4 * n + 127) / 128;
            int tiles = mt1 * 6 + mt2 * 2;
            gemm_dual<<<tiles, 256>>>(hs3, wi3, iouh, n, 768,
                                      &h3[(size_t)choff * KTOT], wf3, fh, 4 * n, 256);
        }
        if (l > 0) combine_fused<<<n / 4, 1024>>>(off, choff);
        else       combine_root<<<1, 256>>>();
    }

    write_out<<<2, 256>>>((float*)d_out);
}

// round 6
// speedup vs baseline: 2.8234x; 1.1185x over previous
#include <cuda_runtime.h>
#include <cuda_bf16.h>
#include <math.h>
#include <stdint.h>

// ---------------------------------------------------------------------------
// ChildSumTreeLSTM via HMMA (mma.sync bf16), fp32 accuracy via 3-term split:
//   A' = [Ah | Al | Ah] (K=768), B' = [Bh | Bh | Bl] (K=768)
// gemm_leaf: leaves only, N=768 (iou, 3j+g interleave), fused activation.
// gemm_big:  internal rows only, N=1024 (4j+g interleave), stores XW.
// ---------------------------------------------------------------------------

#define N_NODES   87381
#define N_INT     21845
#define LEAF_OFF  21845
#define N_LEAVES  65536
#define KTOT      768
#define NCHUNK    24          // 768 / 32
#define AROW_B    80          // smem row stride (bytes) - conflict-free ldmatrix
#define STAGE_B   20480       // 128*80 (A) + 128*80 (B)
#define SPITCH    132         // gemm_big staging pitch (floats)
#define BIG_SMEM  (SPITCH * 128 * 4)      // 67584 >= 3*STAGE_B
#define LSTAGE_B  25600                    // 128*80 (A) + 192*80 (B)
#define LPITCH    196                      // gemm_leaf staging pitch (floats)
#define LEAF_SMEM (LPITCH * 128 * 4)      // 100352 >= 3*LSTAGE_B (76800)

// --------------------------- device scratch --------------------------------
__device__ __align__(256) float         g_XW[(size_t)N_INT * 1024];     // 4j+g
__device__ __align__(256) float         g_c [(size_t)N_NODES * 256];
__device__ __align__(256) __nv_bfloat16 g_h3[(size_t)N_NODES * KTOT];
__device__ __align__(256) __nv_bfloat16 g_x3[(size_t)N_NODES * KTOT];
__device__ __align__(256) __nv_bfloat16 g_hsum3[(size_t)16384 * KTOT];
__device__ __align__(256) float         g_iouh[(size_t)16384 * 768];    // 3j+g
__device__ __align__(256) float         g_fh  [(size_t)65536 * 256];
__device__ __align__(256) __nv_bfloat16 g_Wcat3 [1024 * KTOT];          // 4j+g
__device__ __align__(256) __nv_bfloat16 g_Wiou3 [ 768 * KTOT];          // 3j+g
__device__ __align__(256) __nv_bfloat16 g_Wiouh3[ 768 * KTOT];          // 3j+g
__device__ __align__(256) __nv_bfloat16 g_Wfh3  [ 256 * KTOT];
__device__ float g_bcat[1024];                                          // 4j+g
__device__ float g_b3[768];                                             // 3j+g

// --------------------------- helpers ---------------------------------------
__device__ __forceinline__ float fsig(float v) {
    return __fdividef(1.0f, 1.0f + __expf(-v));
}
__device__ __forceinline__ float ftanh(float v) {
    float a = fabsf(v);
    float e = __expf(-2.0f * a);
    float t = __fdividef(1.0f - e, 1.0f + e);
    return copysignf(t, v);
}
__device__ __forceinline__ void writeA3(__nv_bfloat16* row, int j, float v) {
    __nv_bfloat16 hi = __float2bfloat16(v);
    __nv_bfloat16 lo = __float2bfloat16(v - __bfloat162float(hi));
    row[j] = hi; row[256 + j] = lo; row[512 + j] = hi;
}
__device__ __forceinline__ void writeB3(__nv_bfloat16* row, int j, float v) {
    __nv_bfloat16 hi = __float2bfloat16(v);
    __nv_bfloat16 lo = __float2bfloat16(v - __bfloat162float(hi));
    row[j] = hi; row[256 + j] = hi; row[512 + j] = lo;
}
__device__ __forceinline__ uint32_t smem_u32(const void* p) {
    uint32_t a;
    asm("{ .reg .u64 t; cvta.to.shared.u64 t, %1; cvt.u32.u64 %0, t; }" : "=r"(a) : "l"(p));
    return a;
}
__device__ __forceinline__ void cp_async16(uint32_t dst, const void* src, int sz) {
    asm volatile("cp.async.ca.shared.global [%0], [%1], 16, %2;"
                 :: "r"(dst), "l"(src), "r"(sz) : "memory");
}
__device__ __forceinline__ void ldmatrix_x4(uint32_t* r, uint32_t addr) {
    asm volatile("ldmatrix.sync.aligned.m8n8.x4.shared.b16 {%0,%1,%2,%3}, [%4];"
                 : "=r"(r[0]), "=r"(r[1]), "=r"(r[2]), "=r"(r[3]) : "r"(addr));
}
__device__ __forceinline__ void mma16816(float* c, const uint32_t* a, const uint32_t* b) {
    asm volatile(
        "mma.sync.aligned.m16n8k16.row.col.f32.bf16.bf16.f32 "
        "{%0,%1,%2,%3}, {%4,%5,%6,%7}, {%8,%9}, {%0,%1,%2,%3};"
        : "+f"(c[0]), "+f"(c[1]), "+f"(c[2]), "+f"(c[3])
        : "r"(a[0]), "r"(a[1]), "r"(a[2]), "r"(a[3]), "r"(b[0]), "r"(b[1]));
}

// --------------------------- pack kernels ----------------------------------
__global__ void split_x3(const float* __restrict__ x) {
    const size_t node = blockIdx.x;
    const int j = threadIdx.x;
    writeA3(&g_x3[node * KTOT], j, x[node * 256 + j]);
}

// Wcat rows p = 4j+g (internal x-GEMM)
__global__ void pack_wcat3(const float* __restrict__ Wix, const float* __restrict__ bix,
                           const float* __restrict__ bih,
                           const float* __restrict__ Wfx, const float* __restrict__ bfx,
                           const float* __restrict__ bfh) {
    const int p = blockIdx.x;           // 0..1023
    const int jj = threadIdx.x;
    const int j = p >> 2, g = p & 3;
    float v = (g < 3) ? Wix[(g * 256 + j) * 256 + jj] : Wfx[j * 256 + jj];
    writeB3(&g_Wcat3[(size_t)p * KTOT], jj, v);
    if (jj == 0)
        g_bcat[p] = (g < 3) ? (bix[g * 256 + j] + bih[g * 256 + j]) : (bfx[j] + bfh[j]);
}

// Merged: Wiou3 (leaf GEMM, 3j+g), Wiouh3 (3j+g), Wfh3
__global__ void pack_rest(const float* __restrict__ Wix, const float* __restrict__ bix,
                          const float* __restrict__ bih,
                          const float* __restrict__ Wiouh, const float* __restrict__ Wfh) {
    const int b = blockIdx.x;           // 0..1791
    const int jj = threadIdx.x;
    if (b < 768) {                      // Wiou3 row p = 3j+g
        const int j = b / 3, g = b % 3;
        writeB3(&g_Wiou3[(size_t)b * KTOT], jj, Wix[(g * 256 + j) * 256 + jj]);
        if (jj == 0) g_b3[b] = bix[g * 256 + j] + bih[g * 256 + j];
    } else if (b < 1536) {              // Wiouh3 row p = 3j+g
        const int p = b - 768;
        const int j = p / 3, g = p % 3;
        writeB3(&g_Wiouh3[(size_t)p * KTOT], jj, Wiouh[(g * 256 + j) * 256 + jj]);
    } else {                            // Wfh3 row r
        const int r = b - 1536;
        writeB3(&g_Wfh3[(size_t)r * KTOT], jj, Wfh[r * 256 + jj]);
    }
}

// --------------------------- leaf GEMM (128x192 tiles, fused act) ----------
// C = x_leaf @ Wiou3^T, N=768 (3j+g). Grid (4, 512). 8 warps: 2(m)x4(n),
// warp tile 64x48. 3-stage cp.async. Epilogue: stage->smem, activation.
__global__ __launch_bounds__(256, 1)
void gemm_leaf(const __nv_bfloat16* __restrict__ A,      // g_x3 + LEAF_OFF*KTOT
               const __nv_bfloat16* __restrict__ B) {    // g_Wiou3
    extern __shared__ __align__(16) char smd[];
    const int tid  = threadIdx.x;
    const int wid  = tid >> 5;
    const int lane = tid & 31;
    const int bm = blockIdx.y * 128;
    const int bn = blockIdx.x * 192;
    const int wm = (wid & 1) * 64;
    const int wn = (wid >> 1) * 48;
    const uint32_t sb = smem_u32(smd);

    float acc[4][6][4];
#pragma unroll
    for (int i = 0; i < 4; i++)
#pragma unroll
        for (int n = 0; n < 6; n++)
#pragma unroll
            for (int q = 0; q < 4; q++) acc[i][n][q] = 0.0f;

#define LLOAD(c, st) do {                                                        \
        const int k0 = (c) * 32;                                                 \
        uint32_t ab = sb + (st) * LSTAGE_B;                                      \
        uint32_t bb = ab + 10240;                                                \
        _Pragma("unroll")                                                        \
        for (int s = 0; s < 5; s++) {                                            \
            int id = tid + s * 256;                                              \
            if (id < 512) {                                                      \
                int r = id >> 2, q = id & 3;                                     \
                cp_async16(ab + r * AROW_B + q * 16,                             \
                           A + (size_t)(bm + r) * KTOT + k0 + q * 8, 16);        \
            } else {                                                             \
                int id2 = id - 512;                                              \
                int r = id2 >> 2, q = id2 & 3;                                   \
                cp_async16(bb + r * AROW_B + q * 16,                             \
                           B + (size_t)(bn + r) * KTOT + k0 + q * 8, 16);        \
            }                                                                    \
        }                                                                        \
        asm volatile("cp.async.commit_group;" ::: "memory");                     \
    } while (0)

    LLOAD(0, 0);
    LLOAD(1, 1);
    const uint32_t lrow = lane & 15;
    const uint32_t lcol = (lane >> 4) * 16;

    for (int c = 0; c < NCHUNK; c++) {
        const int st = c % 3;
        if (c + 2 < NCHUNK) {
            LLOAD(c + 2, (c + 2) % 3);
            asm volatile("cp.async.wait_group 2;" ::: "memory");
        } else if (c + 1 < NCHUNK) {
            asm volatile("cp.async.wait_group 1;" ::: "memory");
        } else {
            asm volatile("cp.async.wait_group 0;" ::: "memory");
        }
        __syncthreads();

        const uint32_t abase = sb + st * LSTAGE_B + (wm + lrow) * AROW_B + lcol;
        const uint32_t bbase = sb + st * LSTAGE_B + 10240 + (wn + lrow) * AROW_B + lcol;
#pragma unroll
        for (int ks = 0; ks < 2; ks++) {
            const uint32_t ko = ks * 32;
            uint32_t a[4][4];
#pragma unroll
            for (int i = 0; i < 4; i++)
                ldmatrix_x4(a[i], abase + i * 16 * AROW_B + ko);
            uint32_t bf[6][2];
#pragma unroll
            for (int j = 0; j < 3; j++) {
                uint32_t r[4];
                ldmatrix_x4(r, bbase + j * 16 * AROW_B + ko);
                bf[2 * j][0] = r[0]; bf[2 * j][1] = r[2];
                bf[2 * j + 1][0] = r[1]; bf[2 * j + 1][1] = r[3];
            }
#pragma unroll
            for (int i = 0; i < 4; i++)
#pragma unroll
                for (int n = 0; n < 6; n++)
                    mma16816(acc[i][n], a[i], bf[n]);
        }
        __syncthreads();
    }
#undef LLOAD

    // ---- stage to smem ----
    float* Cs = (float*)smd;
#pragma unroll
    for (int i = 0; i < 4; i++) {
        const int r = wm + i * 16 + (lane >> 2);
#pragma unroll
        for (int n = 0; n < 6; n++) {
            const int col = wn + n * 8 + (lane & 3) * 2;
            *(float2*)(Cs + r * LPITCH + col) = make_float2(acc[i][n][0], acc[i][n][1]);
            *(float2*)(Cs + (r + 8) * LPITCH + col) = make_float2(acc[i][n][2], acc[i][n][3]);
        }
    }
    __syncthreads();

    // ---- leaf activation: 128 rows x 64 features ----
    const int j0 = bn / 3;     // = 64 * blockIdx.x
#pragma unroll 4
    for (int it = 0; it < 32; it++) {
        const int idx = it * 256 + tid;       // 0..8191
        const int r = idx >> 6;               // 0..127
        const int t = idx & 63;               // 0..63
        const float* cr = Cs + r * LPITCH + 3 * t;
        float iv = fsig (cr[0] + g_b3[bn + 3 * t]);
        float ov = fsig (cr[1] + g_b3[bn + 3 * t + 1]);
        float uv = ftanh(cr[2] + g_b3[bn + 3 * t + 2]);
        float cc = iv * uv;
        float hh = ov * ftanh(cc);
        const size_t node = (size_t)LEAF_OFF + bm + r;
        const int j = j0 + t;
        g_c[node * 256 + j] = cc;
        writeA3(&g_h3[node * KTOT], j, hh);
    }
}

// --------------------------- GEMM core (2-stage, used by gemm_dual) --------
__device__ __forceinline__ void gemm_core(const __nv_bfloat16* __restrict__ A,
                                          const __nv_bfloat16* __restrict__ B,
                                          float* __restrict__ C,
                                          int M, int Ntot, int bm, int bn,
                                          char* sm) {
    const int tid  = threadIdx.x;
    const int wid  = tid >> 5;
    const int lane = tid & 31;
    const int wm = (wid >> 1) * 32;
    const int wn = (wid & 1) * 64;
    const uint32_t sb = smem_u32(sm);

    float acc[2][8][4];
#pragma unroll
    for (int i = 0; i < 2; i++)
#pragma unroll
        for (int n = 0; n < 8; n++)
#pragma unroll
            for (int q = 0; q < 4; q++) acc[i][n][q] = 0.0f;

    const int r0 = tid >> 2, q0 = tid & 3;
    const int r1 = (tid + 256) >> 2;
    const int szA0 = (bm + r0 < M) ? 16 : 0;
    const int szA1 = (bm + r1 < M) ? 16 : 0;

#define LOAD2(c, st) do {                                                        \
        const int k0 = (c) * 32;                                                 \
        uint32_t ab = sb + (st) * STAGE_B;                                       \
        uint32_t bb = ab + 10240;                                                \
        cp_async16(ab + r0 * AROW_B + q0 * 16,                                   \
                   A + (size_t)(bm + r0) * KTOT + k0 + q0 * 8, szA0);            \
        cp_async16(ab + r1 * AROW_B + q0 * 16,                                   \
                   A + (size_t)(bm + r1) * KTOT + k0 + q0 * 8, szA1);            \
        cp_async16(bb + r0 * AROW_B + q0 * 16,                                   \
                   B + (size_t)(bn + r0) * KTOT + k0 + q0 * 8, 16);              \
        cp_async16(bb + r1 * AROW_B + q0 * 16,                                   \
                   B + (size_t)(bn + r1) * KTOT + k0 + q0 * 8, 16);              \
        asm volatile("cp.async.commit_group;" ::: "memory");                     \
    } while (0)

    LOAD2(0, 0);
    const uint32_t lrow = lane & 15;
    const uint32_t lcol = (lane >> 4) * 16;

    for (int c = 0; c < NCHUNK; c++) {
        const int st = c & 1;
        if (c + 1 < NCHUNK) {
            LOAD2(c + 1, st ^ 1);
            asm volatile("cp.async.wait_group 1;" ::: "memory");
        } else {
            asm volatile("cp.async.wait_group 0;" ::: "memory");
        }
        __syncthreads();

        const uint32_t abase = sb + st * STAGE_B + (wm + lrow) * AROW_B + lcol;
        const uint32_t bbase = sb + st * STAGE_B + 10240 + (wn + lrow) * AROW_B + lcol;
#pragma unroll
        for (int ks = 0; ks < 2; ks++) {
            const uint32_t ko = ks * 32;
            uint32_t a[2][4];
            ldmatrix_x4(a[0], abase + ko);
            ldmatrix_x4(a[1], abase + 16 * AROW_B + ko);
            uint32_t bf[8][2];
#pragma unroll
            for (int j = 0; j < 4; j++) {
                uint32_t r[4];
                ldmatrix_x4(r, bbase + j * 16 * AROW_B + ko);
                bf[2 * j][0] = r[0]; bf[2 * j][1] = r[2];
                bf[2 * j + 1][0] = r[1]; bf[2 * j + 1][1] = r[3];
            }
#pragma unroll
            for (int i = 0; i < 2; i++)
#pragma unroll
                for (int n = 0; n < 8; n++)
                    mma16816(acc[i][n], a[i], bf[n]);
        }
        __syncthreads();
    }
#undef LOAD2

#pragma unroll
    for (int i = 0; i < 2; i++) {
        const int ra = bm + wm + i * 16 + (lane >> 2);
        const int rb = ra + 8;
#pragma unroll
        for (int n = 0; n < 8; n++) {
            const int col = bn + wn + n * 8 + (lane & 3) * 2;
            if (ra < M)
                *(float2*)(C + (size_t)ra * Ntot + col) =
                    make_float2(acc[i][n][0], acc[i][n][1]);
            if (rb < M)
                *(float2*)(C + (size_t)rb * Ntot + col) =
                    make_float2(acc[i][n][2], acc[i][n][3]);
        }
    }
}

// --------------------------- dual-problem GEMM -----------------------------
__global__ __launch_bounds__(256, 2)
void gemm_dual(const __nv_bfloat16* A1, const __nv_bfloat16* B1, float* C1, int M1, int N1,
               const __nv_bfloat16* A2, const __nv_bfloat16* B2, float* C2, int M2, int N2) {
    __shared__ __align__(16) char sm[2 * STAGE_B];
    const int nt1 = N1 >> 7, mt1 = (M1 + 127) >> 7;
    const int t1 = nt1 * mt1;
    int idx = blockIdx.x;
    if (idx < t1) {
        gemm_core(A1, B1, C1, M1, N1, (idx / nt1) * 128, (idx % nt1) * 128, sm);
    } else {
        idx -= t1;
        const int nt2 = N2 >> 7;
        gemm_core(A2, B2, C2, M2, N2, (idx / nt2) * 128, (idx % nt2) * 128, sm);
    }
}

// --------------------------- internal x-GEMM (3-stage) ---------------------
__global__ __launch_bounds__(256, 2)
void gemm_big(const __nv_bfloat16* __restrict__ A, const __nv_bfloat16* __restrict__ B) {
    extern __shared__ __align__(16) char smd[];
    const int tid  = threadIdx.x;
    const int wid  = tid >> 5;
    const int lane = tid & 31;
    const int bm = blockIdx.y * 128;
    const int bn = blockIdx.x * 128;
    const int wm = (wid >> 1) * 32;
    const int wn = (wid & 1) * 64;
    const int M = N_INT;
    const uint32_t sb = smem_u32(smd);

    float acc[2][8][4];
#pragma unroll
    for (int i = 0; i < 2; i++)
#pragma unroll
        for (int n = 0; n < 8; n++)
#pragma unroll
            for (int q = 0; q < 4; q++) acc[i][n][q] = 0.0f;

    const int r0 = tid >> 2, q0 = tid & 3;
    const int r1 = (tid + 256) >> 2;
    const int szA0 = (bm + r0 < M) ? 16 : 0;
    const int szA1 = (bm + r1 < M) ? 16 : 0;

#define LOAD3(c, st) do {                                                        \
        const int k0 = (c) * 32;                                                 \
        uint32_t ab = sb + (st) * STAGE_B;                                       \
        uint32_t bb = ab + 10240;                                                \
        cp_async16(ab + r0 * AROW_B + q0 * 16,                                   \
                   A + (size_t)(bm + r0) * KTOT + k0 + q0 * 8, szA0);            \
        cp_async16(ab + r1 * AROW_B + q0 * 16,                                   \
                   A + (size_t)(bm + r1) * KTOT + k0 + q0 * 8, szA1);            \
        cp_async16(bb + r0 * AROW_B + q0 * 16,                                   \
                   B + (size_t)(bn + r0) * KTOT + k0 + q0 * 8, 16);              \
        cp_async16(bb + r1 * AROW_B + q0 * 16,                                   \
                   B + (size_t)(bn + r1) * KTOT + k0 + q0 * 8, 16);              \
        asm volatile("cp.async.commit_group;" ::: "memory");                     \
    } while (0)

    LOAD3(0, 0);
    LOAD3(1, 1);
    const uint32_t lrow = lane & 15;
    const uint32_t lcol = (lane >> 4) * 16;

    for (int c = 0; c < NCHUNK; c++) {
        const int st = c % 3;
        if (c + 2 < NCHUNK) {
            LOAD3(c + 2, (c + 2) % 3);
            asm volatile("cp.async.wait_group 2;" ::: "memory");
        } else if (c + 1 < NCHUNK) {
            asm volatile("cp.async.wait_group 1;" ::: "memory");
        } else {
            asm volatile("cp.async.wait_group 0;" ::: "memory");
        }
        __syncthreads();

        const uint32_t abase = sb + st * STAGE_B + (wm + lrow) * AROW_B + lcol;
        const uint32_t bbase = sb + st * STAGE_B + 10240 + (wn + lrow) * AROW_B + lcol;
#pragma unroll
        for (int ks = 0; ks < 2; ks++) {
            const uint32_t ko = ks * 32;
            uint32_t a[2][4];
            ldmatrix_x4(a[0], abase + ko);
            ldmatrix_x4(a[1], abase + 16 * AROW_B + ko);
            uint32_t bf[8][2];
#pragma unroll
            for (int j = 0; j < 4; j++) {
                uint32_t r[4];
                ldmatrix_x4(r, bbase + j * 16 * AROW_B + ko);
                bf[2 * j][0] = r[0]; bf[2 * j][1] = r[2];
                bf[2 * j + 1][0] = r[1]; bf[2 * j + 1][1] = r[3];
            }
#pragma unroll
            for (int i = 0; i < 2; i++)
#pragma unroll
                for (int n = 0; n < 8; n++)
                    mma16816(acc[i][n], a[i], bf[n]);
        }
        __syncthreads();
    }
#undef LOAD3

    // stage C tile, then coalesced float4 XW stores (+bias)
    float* Cs = (float*)smd;
#pragma unroll
    for (int i = 0; i < 2; i++) {
        const int ral = wm + i * 16 + (lane >> 2);
#pragma unroll
        for (int n = 0; n < 8; n++) {
            const int col = wn + n * 8 + (lane & 3) * 2;
            *(float2*)(Cs + ral * SPITCH + col) = make_float2(acc[i][n][0], acc[i][n][1]);
            *(float2*)(Cs + (ral + 8) * SPITCH + col) = make_float2(acc[i][n][2], acc[i][n][3]);
        }
    }
    __syncthreads();

#pragma unroll 4
    for (int it = 0; it < 16; it++) {
        const int idx = it * 256 + tid;
        const int r = idx >> 5;
        const int t = idx & 31;
        const int row = bm + r;
        if (row >= M) continue;
        float4 v = *(float4*)(Cs + r * SPITCH + 4 * t);
        const float4 b = *(const float4*)(g_bcat + bn + 4 * t);
        v.x += b.x; v.y += b.y; v.z += b.z; v.w += b.w;
        *(float4*)(g_XW + (size_t)row * 1024 + bn + 4 * t) = v;
    }
}

// --------------------------- fused combine + parent hsum -------------------
__global__ void combine_fused(int node_off, int child_off) {
    __shared__ float hsm[4][256];
    const int s = threadIdx.x >> 8;
    const int j = threadIdx.x & 255;
    const int k = 4 * blockIdx.x + s;
    const size_t node = (size_t)node_off + k;

    const float4 xw = *(const float4*)(g_XW + node * 1024 + 4 * j);
    const float* iouh = &g_iouh[(size_t)k * 768 + 3 * j];

    float iv = fsig (xw.x + iouh[0]);
    float ov = fsig (xw.y + iouh[1]);
    float uv = ftanh(xw.z + iouh[2]);
    const float fx = xw.w;

    float acc = 0.0f;
#pragma unroll
    for (int b = 0; b < 4; b++) {
        size_t ch = (size_t)child_off + 4 * (size_t)k + b;
        float f = fsig(fx + g_fh[(4 * (size_t)k + b) * 256 + j]);
        acc = fmaf(f, g_c[ch * 256 + j], acc);
    }
    float c = fmaf(iv, uv, acc);
    float h = ov * ftanh(c);
    g_c[node * 256 + j] = c;
    writeA3(&g_h3[node * KTOT], j, h);

    hsm[s][j] = h;
    __syncthreads();
    if (s == 0) {
        float sum = hsm[0][j] + hsm[1][j] + hsm[2][j] + hsm[3][j];
        writeA3(&g_hsum3[(size_t)blockIdx.x * KTOT], j, sum);
    }
}

__global__ void combine_root() {
    const int j = threadIdx.x;
    const float4 xw = *(const float4*)(g_XW + 4 * j);
    const float* iouh = &g_iouh[3 * j];
    float iv = fsig (xw.x + iouh[0]);
    float ov = fsig (xw.y + iouh[1]);
    float uv = ftanh(xw.z + iouh[2]);
    const float fx = xw.w;
    float acc = 0.0f;
#pragma unroll
    for (int b = 0; b < 4; b++) {
        float f = fsig(fx + g_fh[b * 256 + j]);
        acc = fmaf(f, g_c[(1 + b) * 256 + j], acc);
    }
    float c = fmaf(iv, uv, acc);
    float h = ov * ftanh(c);
    g_c[j] = c;
    writeA3(&g_h3[0], j, h);
}

__global__ void gather_hsum_leaf() {
    const int k = blockIdx.x;
    const int j = threadIdx.x;
    const __nv_bfloat16* base = &g_h3[((size_t)LEAF_OFF + 4 * (size_t)k) * KTOT];
    float s = 0.0f;
#pragma unroll
    for (int b = 0; b < 4; b++) {
        const __nv_bfloat16* row = base + (size_t)b * KTOT;
        s += __bfloat162float(row[j]) + __bfloat162float(row[256 + j]);
    }
    writeA3(&g_hsum3[(size_t)k * KTOT], j, s);
}

__global__ void write_out(float* __restrict__ out) {
    int j = threadIdx.x;
    if (blockIdx.x == 0) out[j] = g_c[j];
    else out[256 + j] = __bfloat162float(g_h3[j]) + __bfloat162float(g_h3[256 + j]);
}

// --------------------------- launcher --------------------------------------
extern "C" void kernel_launch(void* const* d_in, const int* in_sizes, int n_in,
                              void* d_out, int out_size) {
    const float* x      = (const float*)d_in[0];
    const float* W_ioux = (const float*)d_in[1];
    const float* b_ioux = (const float*)d_in[2];
    const float* W_iouh = (const float*)d_in[3];
    const float* b_iouh = (const float*)d_in[4];
    const float* W_fx   = (const float*)d_in[5];
    const float* b_fx   = (const float*)d_in[6];
    const float* W_fh   = (const float*)d_in[7];
    const float* b_fh   = (const float*)d_in[8];

    cudaFuncSetAttribute(gemm_big,  cudaFuncAttributeMaxDynamicSharedMemorySize, BIG_SMEM);
    cudaFuncSetAttribute(gemm_leaf, cudaFuncAttributeMaxDynamicSharedMemorySize, LEAF_SMEM);

    __nv_bfloat16 *x3, *h3, *hs3, *wc3, *wl3, *wi3, *wf3;
    float *iouh, *fh;
    cudaGetSymbolAddress((void**)&x3,   g_x3);
    cudaGetSymbolAddress((void**)&h3,   g_h3);
    cudaGetSymbolAddress((void**)&hs3,  g_hsum3);
    cudaGetSymbolAddress((void**)&wc3,  g_Wcat3);
    cudaGetSymbolAddress((void**)&wl3,  g_Wiou3);
    cudaGetSymbolAddress((void**)&wi3,  g_Wiouh3);
    cudaGetSymbolAddress((void**)&wf3,  g_Wfh3);
    cudaGetSymbolAddress((void**)&iouh, g_iouh);
    cudaGetSymbolAddress((void**)&fh,   g_fh);

    // 1-3: pack / split
    split_x3<<<N_NODES, 256>>>(x);
    pack_wcat3<<<1024, 256>>>(W_ioux, b_ioux, b_iouh, W_fx, b_fx, b_fh);
    pack_rest<<<1792, 256>>>(W_ioux, b_ioux, b_iouh, W_iouh, W_fh);

    // 4: leaf GEMM + fused activation (PROFILED LAUNCH)
    {
        dim3 grid(4, N_LEAVES / 128);
        gemm_leaf<<<grid, 256, LEAF_SMEM>>>(&x3[(size_t)LEAF_OFF * KTOT], wl3);
    }

    // 5: internal x-GEMM -> XW
    {
        dim3 grid(8, (N_INT + 127) / 128);
        gemm_big<<<grid, 256, BIG_SMEM>>>(x3, wc3);
    }

    // 6: hsum for level 7
    gather_hsum_leaf<<<16384, 256>>>();

    // internal levels l = 7..0
    for (int l = 7; l >= 0; l--) {
        int n = 1 << (2 * l);
        int off = ((1 << (2 * l)) - 1) / 3;
        int choff = off + n;

        {   // fused dual GEMM: IOUH (n x 768) + FH (4n x 256)
            int mt1 = (n + 127) / 128;
            int mt2 = (4 * n + 127) / 128;
            int tiles = mt1 * 6 + mt2 * 2;
            gemm_dual<<<tiles, 256>>>(hs3, wi3, iouh, n, 768,
                                      &h3[(size_t)choff * KTOT], wf3, fh, 4 * n, 256);
        }
        if (l > 0) combine_fused<<<n / 4, 1024>>>(off, choff);
        else       combine_root<<<1, 256>>>();
    }

    write_out<<<2, 256>>>((float*)d_out);
}

// round 7
// speedup vs baseline: 3.0116x; 1.0667x over previous
#include <cuda_runtime.h>
#include <cuda_bf16.h>
#include <math.h>
#include <stdint.h>

// ---------------------------------------------------------------------------
// ChildSumTreeLSTM via HMMA (mma.sync bf16), fp32 accuracy via 3-term split:
//   A' = [Ah | Al | Ah] (K=768), B' = [Bh | Bh | Bl] (K=768)
// gemm_leaf: leaves only, 128x96 tiles, 2 CTAs/SM, fused activation.
// gemm_big:  internal rows only, N=1024 (4j+g interleave), stores XW.
// ---------------------------------------------------------------------------

#define N_NODES   87381
#define N_INT     21845
#define LEAF_OFF  21845
#define N_LEAVES  65536
#define KTOT      768
#define NCHUNK    24          // 768 / 32
#define AROW_B    80          // smem row stride (bytes) - conflict-free ldmatrix
#define STAGE_B   20480       // 128*80 (A) + 128*80 (B)
#define SPITCH    132         // gemm_big staging pitch (floats)
#define BIG_SMEM  (SPITCH * 128 * 4)      // 67584 >= 3*STAGE_B
#define LSTAGE_B  17920                    // 128*80 (A) + 96*80 (B)
#define LPITCH    100                      // gemm_leaf staging pitch (floats)
#define LEAF_SMEM (3 * LSTAGE_B)          // 53760 >= 128*LPITCH*4 (51200)

// --------------------------- device scratch --------------------------------
__device__ __align__(256) float         g_XW[(size_t)N_INT * 1024];     // 4j+g
__device__ __align__(256) float         g_c [(size_t)N_NODES * 256];
__device__ __align__(256) __nv_bfloat16 g_h3[(size_t)N_NODES * KTOT];
__device__ __align__(256) __nv_bfloat16 g_x3[(size_t)N_NODES * KTOT];
__device__ __align__(256) __nv_bfloat16 g_hsum3[(size_t)16384 * KTOT];
__device__ __align__(256) float         g_iouh[(size_t)16384 * 768];    // 3j+g
__device__ __align__(256) float         g_fh  [(size_t)65536 * 256];
__device__ __align__(256) __nv_bfloat16 g_Wcat3 [1024 * KTOT];          // 4j+g
__device__ __align__(256) __nv_bfloat16 g_Wiou3 [ 768 * KTOT];          // 3j+g
__device__ __align__(256) __nv_bfloat16 g_Wiouh3[ 768 * KTOT];          // 3j+g
__device__ __align__(256) __nv_bfloat16 g_Wfh3  [ 256 * KTOT];
__device__ float g_bcat[1024];                                          // 4j+g
__device__ float g_b3[768];                                             // 3j+g

// --------------------------- helpers ---------------------------------------
__device__ __forceinline__ float fsig(float v) {
    return __fdividef(1.0f, 1.0f + __expf(-v));
}
__device__ __forceinline__ float ftanh(float v) {
    float a = fabsf(v);
    float e = __expf(-2.0f * a);
    float t = __fdividef(1.0f - e, 1.0f + e);
    return copysignf(t, v);
}
__device__ __forceinline__ void writeA3(__nv_bfloat16* row, int j, float v) {
    __nv_bfloat16 hi = __float2bfloat16(v);
    __nv_bfloat16 lo = __float2bfloat16(v - __bfloat162float(hi));
    row[j] = hi; row[256 + j] = lo; row[512 + j] = hi;
}
__device__ __forceinline__ void writeB3(__nv_bfloat16* row, int j, float v) {
    __nv_bfloat16 hi = __float2bfloat16(v);
    __nv_bfloat16 lo = __float2bfloat16(v - __bfloat162float(hi));
    row[j] = hi; row[256 + j] = hi; row[512 + j] = lo;
}
__device__ __forceinline__ uint32_t pack_bf2(float a, float b) {
    __nv_bfloat162 p = __floats2bfloat162_rn(a, b);
    return *reinterpret_cast<uint32_t*>(&p);
}
__device__ __forceinline__ uint32_t smem_u32(const void* p) {
    uint32_t a;
    asm("{ .reg .u64 t; cvta.to.shared.u64 t, %1; cvt.u32.u64 %0, t; }" : "=r"(a) : "l"(p));
    return a;
}
__device__ __forceinline__ void cp_async16(uint32_t dst, const void* src, int sz) {
    asm volatile("cp.async.ca.shared.global [%0], [%1], 16, %2;"
                 :: "r"(dst), "l"(src), "r"(sz) : "memory");
}
__device__ __forceinline__ void ldmatrix_x4(uint32_t* r, uint32_t addr) {
    asm volatile("ldmatrix.sync.aligned.m8n8.x4.shared.b16 {%0,%1,%2,%3}, [%4];"
                 : "=r"(r[0]), "=r"(r[1]), "=r"(r[2]), "=r"(r[3]) : "r"(addr));
}
__device__ __forceinline__ void mma16816(float* c, const uint32_t* a, const uint32_t* b) {
    asm volatile(
        "mma.sync.aligned.m16n8k16.row.col.f32.bf16.bf16.f32 "
        "{%0,%1,%2,%3}, {%4,%5,%6,%7}, {%8,%9}, {%0,%1,%2,%3};"
        : "+f"(c[0]), "+f"(c[1]), "+f"(c[2]), "+f"(c[3])
        : "r"(a[0]), "r"(a[1]), "r"(a[2]), "r"(a[3]), "r"(b[0]), "r"(b[1]));
}

// --------------------------- pack kernels ----------------------------------
__global__ void split_x3(const float* __restrict__ x) {
    const size_t node = blockIdx.x;
    const int j = threadIdx.x;
    writeA3(&g_x3[node * KTOT], j, x[node * 256 + j]);
}

// Wcat rows p = 4j+g (internal x-GEMM)
__global__ void pack_wcat3(const float* __restrict__ Wix, const float* __restrict__ bix,
                           const float* __restrict__ bih,
                           const float* __restrict__ Wfx, const float* __restrict__ bfx,
                           const float* __restrict__ bfh) {
    const int p = blockIdx.x;           // 0..1023
    const int jj = threadIdx.x;
    const int j = p >> 2, g = p & 3;
    float v = (g < 3) ? Wix[(g * 256 + j) * 256 + jj] : Wfx[j * 256 + jj];
    writeB3(&g_Wcat3[(size_t)p * KTOT], jj, v);
    if (jj == 0)
        g_bcat[p] = (g < 3) ? (bix[g * 256 + j] + bih[g * 256 + j]) : (bfx[j] + bfh[j]);
}

// Merged: Wiou3 (leaf GEMM, 3j+g), Wiouh3 (3j+g), Wfh3
__global__ void pack_rest(const float* __restrict__ Wix, const float* __restrict__ bix,
                          const float* __restrict__ bih,
                          const float* __restrict__ Wiouh, const float* __restrict__ Wfh) {
    const int b = blockIdx.x;           // 0..1791
    const int jj = threadIdx.x;
    if (b < 768) {                      // Wiou3 row p = 3j+g
        const int j = b / 3, g = b % 3;
        writeB3(&g_Wiou3[(size_t)b * KTOT], jj, Wix[(g * 256 + j) * 256 + jj]);
        if (jj == 0) g_b3[b] = bix[g * 256 + j] + bih[g * 256 + j];
    } else if (b < 1536) {              // Wiouh3 row p = 3j+g
        const int p = b - 768;
        const int j = p / 3, g = p % 3;
        writeB3(&g_Wiouh3[(size_t)p * KTOT], jj, Wiouh[(g * 256 + j) * 256 + jj]);
    } else {                            // Wfh3 row r
        const int r = b - 1536;
        writeB3(&g_Wfh3[(size_t)r * KTOT], jj, Wfh[r * 256 + jj]);
    }
}

// --------------------------- leaf GEMM (128x96 tiles, 2 CTA/SM) ------------
// C = x_leaf @ Wiou3^T, N=768 (3j+g). Grid (8, 512). 8 warps: 4(m)x2(n),
// warp tile 32x48. 3-stage cp.async. Fused leaf activation epilogue.
__global__ __launch_bounds__(256, 2)
void gemm_leaf(const __nv_bfloat16* __restrict__ A,      // g_x3 + LEAF_OFF*KTOT
               const __nv_bfloat16* __restrict__ B) {    // g_Wiou3
    extern __shared__ __align__(16) char smd[];
    const int tid  = threadIdx.x;
    const int wid  = tid >> 5;
    const int lane = tid & 31;
    const int bm = blockIdx.y * 128;
    const int bn = blockIdx.x * 96;
    const int wm = (wid >> 1) * 32;
    const int wn = (wid & 1) * 48;
    const uint32_t sb = smem_u32(smd);

    float acc[2][6][4];
#pragma unroll
    for (int i = 0; i < 2; i++)
#pragma unroll
        for (int n = 0; n < 6; n++)
#pragma unroll
            for (int q = 0; q < 4; q++) acc[i][n][q] = 0.0f;

#define LLOAD(c, st) do {                                                        \
        const int k0 = (c) * 32;                                                 \
        uint32_t ab = sb + (st) * LSTAGE_B;                                      \
        uint32_t bb = ab + 10240;                                                \
        _Pragma("unroll")                                                        \
        for (int s = 0; s < 4; s++) {                                            \
            int id = tid + s * 256;                                              \
            if (id < 512) {                                                      \
                int r = id >> 2, q = id & 3;                                     \
                cp_async16(ab + r * AROW_B + q * 16,                             \
                           A + (size_t)(bm + r) * KTOT + k0 + q * 8, 16);        \
            } else if (id < 896) {                                               \
                int id2 = id - 512;                                              \
                int r = id2 >> 2, q = id2 & 3;                                   \
                cp_async16(bb + r * AROW_B + q * 16,                             \
                           B + (size_t)(bn + r) * KTOT + k0 + q * 8, 16);        \
            }                                                                    \
        }                                                                        \
        asm volatile("cp.async.commit_group;" ::: "memory");                     \
    } while (0)

    LLOAD(0, 0);
    LLOAD(1, 1);
    const uint32_t lrow = lane & 15;
    const uint32_t lcol = (lane >> 4) * 16;

    for (int c = 0; c < NCHUNK; c++) {
        const int st = c % 3;
        if (c + 2 < NCHUNK) {
            LLOAD(c + 2, (c + 2) % 3);
            asm volatile("cp.async.wait_group 2;" ::: "memory");
        } else if (c + 1 < NCHUNK) {
            asm volatile("cp.async.wait_group 1;" ::: "memory");
        } else {
            asm volatile("cp.async.wait_group 0;" ::: "memory");
        }
        __syncthreads();

        const uint32_t abase = sb + st * LSTAGE_B + (wm + lrow) * AROW_B + lcol;
        const uint32_t bbase = sb + st * LSTAGE_B + 10240 + (wn + lrow) * AROW_B + lcol;
#pragma unroll
        for (int ks = 0; ks < 2; ks++) {
            const uint32_t ko = ks * 32;
            uint32_t a[2][4];
            ldmatrix_x4(a[0], abase + ko);
            ldmatrix_x4(a[1], abase + 16 * AROW_B + ko);
            uint32_t bf[6][2];
#pragma unroll
            for (int j = 0; j < 3; j++) {
                uint32_t r[4];
                ldmatrix_x4(r, bbase + j * 16 * AROW_B + ko);
                bf[2 * j][0] = r[0]; bf[2 * j][1] = r[2];
                bf[2 * j + 1][0] = r[1]; bf[2 * j + 1][1] = r[3];
            }
#pragma unroll
            for (int i = 0; i < 2; i++)
#pragma unroll
                for (int n = 0; n < 6; n++)
                    mma16816(acc[i][n], a[i], bf[n]);
        }
        __syncthreads();
    }
#undef LLOAD

    // ---- stage tile to smem (aliases pipeline buffers) ----
    float* Cs = (float*)smd;
#pragma unroll
    for (int i = 0; i < 2; i++) {
        const int r = wm + i * 16 + (lane >> 2);
#pragma unroll
        for (int n = 0; n < 6; n++) {
            const int col = wn + n * 8 + (lane & 3) * 2;
            *(float2*)(Cs + r * LPITCH + col) = make_float2(acc[i][n][0], acc[i][n][1]);
            *(float2*)(Cs + (r + 8) * LPITCH + col) = make_float2(acc[i][n][2], acc[i][n][3]);
        }
    }
    __syncthreads();

    // ---- leaf activation: 128 rows x 32 features, 2 features per thread ----
    const int j0 = 32 * blockIdx.x;
#pragma unroll 2
    for (int it = 0; it < 8; it++) {
        const int idx = it * 256 + tid;       // 0..2047
        const int r = idx >> 4;               // 0..127
        const int p = idx & 15;               // pair 0..15
        const int t = 2 * p;
        const float* cr = Cs + r * LPITCH + 3 * t;
        const float* bb = g_b3 + bn + 3 * t;
        float i0 = fsig (cr[0] + bb[0]);
        float o0 = fsig (cr[1] + bb[1]);
        float u0 = ftanh(cr[2] + bb[2]);
        float c0 = i0 * u0;
        float h0 = o0 * ftanh(c0);
        float i1 = fsig (cr[3] + bb[3]);
        float o1 = fsig (cr[4] + bb[4]);
        float u1 = ftanh(cr[5] + bb[5]);
        float c1 = i1 * u1;
        float h1 = o1 * ftanh(c1);

        const size_t node = (size_t)LEAF_OFF + bm + r;
        const int j = j0 + t;
        *(float2*)(g_c + node * 256 + j) = make_float2(c0, c1);

        __nv_bfloat16 hh0 = __float2bfloat16(h0);
        __nv_bfloat16 hh1 = __float2bfloat16(h1);
        float l0 = h0 - __bfloat162float(hh0);
        float l1 = h1 - __bfloat162float(hh1);
        uint32_t hiw; { __nv_bfloat162 p2 = {hh0, hh1}; hiw = *reinterpret_cast<uint32_t*>(&p2); }
        uint32_t low = pack_bf2(l0, l1);
        uint32_t* hrow = (uint32_t*)(g_h3 + node * KTOT + j);
        hrow[0] = hiw;                 // hi at j
        hrow[128] = low;               // lo at 256+j
        hrow[256] = hiw;               // hi at 512+j
    }
}

// --------------------------- GEMM core (2-stage, used by gemm_dual) --------
__device__ __forceinline__ void gemm_core(const __nv_bfloat16* __restrict__ A,
                                          const __nv_bfloat16* __restrict__ B,
                                          float* __restrict__ C,
                                          int M, int Ntot, int bm, int bn,
                                          char* sm) {
    const int tid  = threadIdx.x;
    const int wid  = tid >> 5;
    const int lane = tid & 31;
    const int wm = (wid >> 1) * 32;
    const int wn = (wid & 1) * 64;
    const uint32_t sb = smem_u32(sm);

    float acc[2][8][4];
#pragma unroll
    for (int i = 0; i < 2; i++)
#pragma unroll
        for (int n = 0; n < 8; n++)
#pragma unroll
            for (int q = 0; q < 4; q++) acc[i][n][q] = 0.0f;

    const int r0 = tid >> 2, q0 = tid & 3;
    const int r1 = (tid + 256) >> 2;
    const int szA0 = (bm + r0 < M) ? 16 : 0;
    const int szA1 = (bm + r1 < M) ? 16 : 0;

#define LOAD2(c, st) do {                                                        \
        const int k0 = (c) * 32;                                                 \
        uint32_t ab = sb + (st) * STAGE_B;                                       \
        uint32_t bb = ab + 10240;                                                \
        cp_async16(ab + r0 * AROW_B + q0 * 16,                                   \
                   A + (size_t)(bm + r0) * KTOT + k0 + q0 * 8, szA0);            \
        cp_async16(ab + r1 * AROW_B + q0 * 16,                                   \
                   A + (size_t)(bm + r1) * KTOT + k0 + q0 * 8, szA1);            \
        cp_async16(bb + r0 * AROW_B + q0 * 16,                                   \
                   B + (size_t)(bn + r0) * KTOT + k0 + q0 * 8, 16);              \
        cp_async16(bb + r1 * AROW_B + q0 * 16,                                   \
                   B + (size_t)(bn + r1) * KTOT + k0 + q0 * 8, 16);              \
        asm volatile("cp.async.commit_group;" ::: "memory");                     \
    } while (0)

    LOAD2(0, 0);
    const uint32_t lrow = lane & 15;
    const uint32_t lcol = (lane >> 4) * 16;

    for (int c = 0; c < NCHUNK; c++) {
        const int st = c & 1;
        if (c + 1 < NCHUNK) {
            LOAD2(c + 1, st ^ 1);
            asm volatile("cp.async.wait_group 1;" ::: "memory");
        } else {
            asm volatile("cp.async.wait_group 0;" ::: "memory");
        }
        __syncthreads();

        const uint32_t abase = sb + st * STAGE_B + (wm + lrow) * AROW_B + lcol;
        const uint32_t bbase = sb + st * STAGE_B + 10240 + (wn + lrow) * AROW_B + lcol;
#pragma unroll
        for (int ks = 0; ks < 2; ks++) {
            const uint32_t ko = ks * 32;
            uint32_t a[2][4];
            ldmatrix_x4(a[0], abase + ko);
            ldmatrix_x4(a[1], abase + 16 * AROW_B + ko);
            uint32_t bf[8][2];
#pragma unroll
            for (int j = 0; j < 4; j++) {
                uint32_t r[4];
                ldmatrix_x4(r, bbase + j * 16 * AROW_B + ko);
                bf[2 * j][0] = r[0]; bf[2 * j][1] = r[2];
                bf[2 * j + 1][0] = r[1]; bf[2 * j + 1][1] = r[3];
            }
#pragma unroll
            for (int i = 0; i < 2; i++)
#pragma unroll
                for (int n = 0; n < 8; n++)
                    mma16816(acc[i][n], a[i], bf[n]);
        }
        __syncthreads();
    }
#undef LOAD2

#pragma unroll
    for (int i = 0; i < 2; i++) {
        const int ra = bm + wm + i * 16 + (lane >> 2);
        const int rb = ra + 8;
#pragma unroll
        for (int n = 0; n < 8; n++) {
            const int col = bn + wn + n * 8 + (lane & 3) * 2;
            if (ra < M)
                *(float2*)(C + (size_t)ra * Ntot + col) =
                    make_float2(acc[i][n][0], acc[i][n][1]);
            if (rb < M)
                *(float2*)(C + (size_t)rb * Ntot + col) =
                    make_float2(acc[i][n][2], acc[i][n][3]);
        }
    }
}

// --------------------------- dual-problem GEMM -----------------------------
__global__ __launch_bounds__(256, 2)
void gemm_dual(const __nv_bfloat16* A1, const __nv_bfloat16* B1, float* C1, int M1, int N1,
               const __nv_bfloat16* A2, const __nv_bfloat16* B2, float* C2, int M2, int N2) {
    __shared__ __align__(16) char sm[2 * STAGE_B];
    const int nt1 = N1 >> 7, mt1 = (M1 + 127) >> 7;
    const int t1 = nt1 * mt1;
    int idx = blockIdx.x;
    if (idx < t1) {
        gemm_core(A1, B1, C1, M1, N1, (idx / nt1) * 128, (idx % nt1) * 128, sm);
    } else {
        idx -= t1;
        const int nt2 = N2 >> 7;
        gemm_core(A2, B2, C2, M2, N2, (idx / nt2) * 128, (idx % nt2) * 128, sm);
    }
}

// --------------------------- internal x-GEMM (3-stage) ---------------------
__global__ __launch_bounds__(256, 2)
void gemm_big(const __nv_bfloat16* __restrict__ A, const __nv_bfloat16* __restrict__ B) {
    extern __shared__ __align__(16) char smd[];
    const int tid  = threadIdx.x;
    const int wid  = tid >> 5;
    const int lane = tid & 31;
    const int bm = blockIdx.y * 128;
    const int bn = blockIdx.x * 128;
    const int wm = (wid >> 1) * 32;
    const int wn = (wid & 1) * 64;
    const int M = N_INT;
    const uint32_t sb = smem_u32(smd);

    float acc[2][8][4];
#pragma unroll
    for (int i = 0; i < 2; i++)
#pragma unroll
        for (int n = 0; n < 8; n++)
#pragma unroll
            for (int q = 0; q < 4; q++) acc[i][n][q] = 0.0f;

    const int r0 = tid >> 2, q0 = tid & 3;
    const int r1 = (tid + 256) >> 2;
    const int szA0 = (bm + r0 < M) ? 16 : 0;
    const int szA1 = (bm + r1 < M) ? 16 : 0;

#define LOAD3(c, st) do {                                                        \
        const int k0 = (c) * 32;                                                 \
        uint32_t ab = sb + (st) * STAGE_B;                                       \
        uint32_t bb = ab + 10240;                                                \
        cp_async16(ab + r0 * AROW_B + q0 * 16,                                   \
                   A + (size_t)(bm + r0) * KTOT + k0 + q0 * 8, szA0);            \
        cp_async16(ab + r1 * AROW_B + q0 * 16,                                   \
                   A + (size_t)(bm + r1) * KTOT + k0 + q0 * 8, szA1);            \
        cp_async16(bb + r0 * AROW_B + q0 * 16,                                   \
                   B + (size_t)(bn + r0) * KTOT + k0 + q0 * 8, 16);              \
        cp_async16(bb + r1 * AROW_B + q0 * 16,                                   \
                   B + (size_t)(bn + r1) * KTOT + k0 + q0 * 8, 16);              \
        asm volatile("cp.async.commit_group;" ::: "memory");                     \
    } while (0)

    LOAD3(0, 0);
    LOAD3(1, 1);
    const uint32_t lrow = lane & 15;
    const uint32_t lcol = (lane >> 4) * 16;

    for (int c = 0; c < NCHUNK; c++) {
        const int st = c % 3;
        if (c + 2 < NCHUNK) {
            LOAD3(c + 2, (c + 2) % 3);
            asm volatile("cp.async.wait_group 2;" ::: "memory");
        } else if (c + 1 < NCHUNK) {
            asm volatile("cp.async.wait_group 1;" ::: "memory");
        } else {
            asm volatile("cp.async.wait_group 0;" ::: "memory");
        }
        __syncthreads();

        const uint32_t abase = sb + st * STAGE_B + (wm + lrow) * AROW_B + lcol;
        const uint32_t bbase = sb + st * STAGE_B + 10240 + (wn + lrow) * AROW_B + lcol;
#pragma unroll
        for (int ks = 0; ks < 2; ks++) {
            const uint32_t ko = ks * 32;
            uint32_t a[2][4];
            ldmatrix_x4(a[0], abase + ko);
            ldmatrix_x4(a[1], abase + 16 * AROW_B + ko);
            uint32_t bf[8][2];
#pragma unroll
            for (int j = 0; j < 4; j++) {
                uint32_t r[4];
                ldmatrix_x4(r, bbase + j * 16 * AROW_B + ko);
                bf[2 * j][0] = r[0]; bf[2 * j][1] = r[2];
                bf[2 * j + 1][0] = r[1]; bf[2 * j + 1][1] = r[3];
            }
#pragma unroll
            for (int i = 0; i < 2; i++)
#pragma unroll
                for (int n = 0; n < 8; n++)
                    mma16816(acc[i][n], a[i], bf[n]);
        }
        __syncthreads();
    }
#undef LOAD3

    // stage C tile, then coalesced float4 XW stores (+bias)
    float* Cs = (float*)smd;
#pragma unroll
    for (int i = 0; i < 2; i++) {
        const int ral = wm + i * 16 + (lane >> 2);
#pragma unroll
        for (int n = 0; n < 8; n++) {
            const int col = wn + n * 8 + (lane & 3) * 2;
            *(float2*)(Cs + ral * SPITCH + col) = make_float2(acc[i][n][0], acc[i][n][1]);
            *(float2*)(Cs + (ral + 8) * SPITCH + col) = make_float2(acc[i][n][2], acc[i][n][3]);
        }
    }
    __syncthreads();

#pragma unroll 4
    for (int it = 0; it < 16; it++) {
        const int idx = it * 256 + tid;
        const int r = idx >> 5;
        const int t = idx & 31;
        const int row = bm + r;
        if (row >= M) continue;
        float4 v = *(float4*)(Cs + r * SPITCH + 4 * t);
        const float4 b = *(const float4*)(g_bcat + bn + 4 * t);
        v.x += b.x; v.y += b.y; v.z += b.z; v.w += b.w;
        *(float4*)(g_XW + (size_t)row * 1024 + bn + 4 * t) = v;
    }
}

// --------------------------- fused combine + parent hsum -------------------
__global__ void combine_fused(int node_off, int child_off) {
    __shared__ float hsm[4][256];
    const int s = threadIdx.x >> 8;
    const int j = threadIdx.x & 255;
    const int k = 4 * blockIdx.x + s;
    const size_t node = (size_t)node_off + k;

    const float4 xw = *(const float4*)(g_XW + node * 1024 + 4 * j);
    const float* iouh = &g_iouh[(size_t)k * 768 + 3 * j];

    float iv = fsig (xw.x + iouh[0]);
    float ov = fsig (xw.y + iouh[1]);
    float uv = ftanh(xw.z + iouh[2]);
    const float fx = xw.w;

    float acc = 0.0f;
#pragma unroll
    for (int b = 0; b < 4; b++) {
        size_t ch = (size_t)child_off + 4 * (size_t)k + b;
        float f = fsig(fx + g_fh[(4 * (size_t)k + b) * 256 + j]);
        acc = fmaf(f, g_c[ch * 256 + j], acc);
    }
    float c = fmaf(iv, uv, acc);
    float h = ov * ftanh(c);
    g_c[node * 256 + j] = c;
    writeA3(&g_h3[node * KTOT], j, h);

    hsm[s][j] = h;
    __syncthreads();
    if (s == 0) {
        float sum = hsm[0][j] + hsm[1][j] + hsm[2][j] + hsm[3][j];
        writeA3(&g_hsum3[(size_t)blockIdx.x * KTOT], j, sum);
    }
}

__global__ void combine_root() {
    const int j = threadIdx.x;
    const float4 xw = *(const float4*)(g_XW + 4 * j);
    const float* iouh = &g_iouh[3 * j];
    float iv = fsig (xw.x + iouh[0]);
    float ov = fsig (xw.y + iouh[1]);
    float uv = ftanh(xw.z + iouh[2]);
    const float fx = xw.w;
    float acc = 0.0f;
#pragma unroll
    for (int b = 0; b < 4; b++) {
        float f = fsig(fx + g_fh[b * 256 + j]);
        acc = fmaf(f, g_c[(1 + b) * 256 + j], acc);
    }
    float c = fmaf(iv, uv, acc);
    float h = ov * ftanh(c);
    g_c[j] = c;
    writeA3(&g_h3[0], j, h);
}

__global__ void gather_hsum_leaf() {
    const int k = blockIdx.x;
    const int j = threadIdx.x;
    const __nv_bfloat16* base = &g_h3[((size_t)LEAF_OFF + 4 * (size_t)k) * KTOT];
    float s = 0.0f;
#pragma unroll
    for (int b = 0; b < 4; b++) {
        const __nv_bfloat16* row = base + (size_t)b * KTOT;
        s += __bfloat162float(row[j]) + __bfloat162float(row[256 + j]);
    }
    writeA3(&g_hsum3[(size_t)k * KTOT], j, s);
}

__global__ void write_out(float* __restrict__ out) {
    int j = threadIdx.x;
    if (blockIdx.x == 0) out[j] = g_c[j];
    else out[256 + j] = __bfloat162float(g_h3[j]) + __bfloat162float(g_h3[256 + j]);
}

// --------------------------- launcher --------------------------------------
extern "C" void kernel_launch(void* const* d_in, const int* in_sizes, int n_in,
                              void* d_out, int out_size) {
    const float* x      = (const float*)d_in[0];
    const float* W_ioux = (const float*)d_in[1];
    const float* b_ioux = (const float*)d_in[2];
    const float* W_iouh = (const float*)d_in[3];
    const float* b_iouh = (const float*)d_in[4];
    const float* W_fx   = (const float*)d_in[5];
    const float* b_fx   = (const float*)d_in[6];
    const float* W_fh   = (const float*)d_in[7];
    const float* b_fh   = (const float*)d_in[8];

    cudaFuncSetAttribute(gemm_big,  cudaFuncAttributeMaxDynamicSharedMemorySize, BIG_SMEM);
    cudaFuncSetAttribute(gemm_leaf, cudaFuncAttributeMaxDynamicSharedMemorySize, LEAF_SMEM);

    __nv_bfloat16 *x3, *h3, *hs3, *wc3, *wl3, *wi3, *wf3;
    float *iouh, *fh;
    cudaGetSymbolAddress((void**)&x3,   g_x3);
    cudaGetSymbolAddress((void**)&h3,   g_h3);
    cudaGetSymbolAddress((void**)&hs3,  g_hsum3);
    cudaGetSymbolAddress((void**)&wc3,  g_Wcat3);
    cudaGetSymbolAddress((void**)&wl3,  g_Wiou3);
    cudaGetSymbolAddress((void**)&wi3,  g_Wiouh3);
    cudaGetSymbolAddress((void**)&wf3,  g_Wfh3);
    cudaGetSymbolAddress((void**)&iouh, g_iouh);
    cudaGetSymbolAddress((void**)&fh,   g_fh);

    // 1-3: pack / split
    split_x3<<<N_NODES, 256>>>(x);
    pack_wcat3<<<1024, 256>>>(W_ioux, b_ioux, b_iouh, W_fx, b_fx, b_fh);
    pack_rest<<<1792, 256>>>(W_ioux, b_ioux, b_iouh, W_iouh, W_fh);

    // 4: leaf GEMM + fused activation (PROFILED LAUNCH)
    {
        dim3 grid(8, N_LEAVES / 128);
        gemm_leaf<<<grid, 256, LEAF_SMEM>>>(&x3[(size_t)LEAF_OFF * KTOT], wl3);
    }

    // 5: internal x-GEMM -> XW
    {
        dim3 grid(8, (N_INT + 127) / 128);
        gemm_big<<<grid, 256, BIG_SMEM>>>(x3, wc3);
    }

    // 6: hsum for level 7
    gather_hsum_leaf<<<16384, 256>>>();

    // internal levels l = 7..0
    for (int l = 7; l >= 0; l--) {
        int n = 1 << (2 * l);
        int off = ((1 << (2 * l)) - 1) / 3;
        int choff = off + n;

        {   // fused dual GEMM: IOUH (n x 768) + FH (4n x 256)
            int mt1 = (n + 127) / 128;
            int mt2 = (4 * n + 127) / 128;
            int tiles = mt1 * 6 + mt2 * 2;
            gemm_dual<<<tiles, 256>>>(hs3, wi3, iouh, n, 768,
                                      &h3[(size_t)choff * KTOT], wf3, fh, 4 * n, 256);
        }
        if (l > 0) combine_fused<<<n / 4, 1024>>>(off, choff);
        else       combine_root<<<1, 256>>>();
    }

    write_out<<<2, 256>>>((float*)d_out);
}